// round 15
// baseline (speedup 1.0000x reference)
#include <cuda_runtime.h>
#include <cuda_bf16.h>
#include <cstdint>

#define B_SZ   16
#define NPTS   32768
#define DFEAT  256
#define EDIM   512
#define KSEL   512
#define HEADS  8
#define DH     64
#define TOUT   16
#define CAND_MAX 4096

// ------------------------- scratch (device globals, no allocs) ----------------
__device__ int   g_idx[B_SZ * KSEL];
__device__ unsigned int g_hist[B_SZ * 8 * 256];
__device__ int   g_cnt[B_SZ];
__device__ unsigned long long g_cand[B_SZ * CAND_MAX];
__device__ __nv_bfloat16 g_ahi[B_SZ * KSEL * DFEAT];
__device__ __nv_bfloat16 g_alo[B_SZ * KSEL * DFEAT];
__device__ __nv_bfloat16 g_wphi[EDIM * DFEAT];
__device__ __nv_bfloat16 g_wplo[EDIM * DFEAT];
__device__ __nv_bfloat16 g_wqhi[EDIM * EDIM];
__device__ __nv_bfloat16 g_wqlo[EDIM * EDIM];
__device__ __nv_bfloat16 g_wkvhi[2 * EDIM * EDIM];
__device__ __nv_bfloat16 g_wkvlo[2 * EDIM * EDIM];
__device__ __nv_bfloat16 g_wohi[EDIM * EDIM];
__device__ __nv_bfloat16 g_wolo[EDIM * EDIM];
__device__ __nv_bfloat16 g_wfhi[EDIM * EDIM];
__device__ __nv_bfloat16 g_wflo[EDIM * EDIM];
__device__ __nv_bfloat16 g_xhi[B_SZ * KSEL * EDIM];
__device__ __nv_bfloat16 g_xlo[B_SZ * KSEL * EDIM];
__device__ float g_kv[B_SZ * KSEL * 2 * EDIM];   // row stride 1024: [k | v]
__device__ float g_xq[B_SZ * TOUT * EDIM];
__device__ float g_q [B_SZ * TOUT * EDIM];
__device__ __nv_bfloat16 g_ohi[B_SZ * TOUT * EDIM];
__device__ __nv_bfloat16 g_olo[B_SZ * TOUT * EDIM];
__device__ float g_o2[B_SZ * TOUT * EDIM];
__device__ float g_y [B_SZ * TOUT * EDIM];
__device__ __nv_bfloat16 g_yhi[B_SZ * TOUT * EDIM];
__device__ __nv_bfloat16 g_ylo[B_SZ * TOUT * EDIM];

// ------------------------- helpers -------------------------------------------
__device__ __forceinline__ uint32_t smem_u32(const void* p) {
    uint32_t a;
    asm("{ .reg .u64 t; cvta.to.shared.u64 t, %1; cvt.u32.u64 %0, t; }" : "=r"(a) : "l"(p));
    return a;
}
__device__ __forceinline__ void ldsm4(uint32_t (&r)[4], uint32_t addr) {
    asm volatile("ldmatrix.sync.aligned.m8n8.x4.shared.b16 {%0,%1,%2,%3}, [%4];"
                 : "=r"(r[0]), "=r"(r[1]), "=r"(r[2]), "=r"(r[3]) : "r"(addr));
}
__device__ __forceinline__ void mma_bf16(float (&d)[4], const uint32_t (&a)[4],
                                         uint32_t b0, uint32_t b1) {
    asm volatile("mma.sync.aligned.m16n8k16.row.col.f32.bf16.bf16.f32 "
                 "{%0,%1,%2,%3}, {%4,%5,%6,%7}, {%8,%9}, {%0,%1,%2,%3};"
                 : "+f"(d[0]), "+f"(d[1]), "+f"(d[2]), "+f"(d[3])
                 : "r"(a[0]), "r"(a[1]), "r"(a[2]), "r"(a[3]), "r"(b0), "r"(b1));
}
#define CP_ASYNC16(dst, src) \
    asm volatile("cp.async.cg.shared.global [%0], [%1], 16;" :: "r"(dst), "l"(src))
#define CP_COMMIT() asm volatile("cp.async.commit_group;")
#define CP_WAIT(n)  asm volatile("cp.async.wait_group %0;" :: "n"(n))

__device__ __forceinline__ unsigned int f2u(float f) {
    unsigned int u = __float_as_uint(f);
    return (u & 0x80000000u) ? ~u : (u | 0x80000000u);
}
__device__ __forceinline__ void split_bf16(float f, __nv_bfloat16& h, __nv_bfloat16& l) {
    h = __float2bfloat16_rn(f);
    l = __float2bfloat16_rn(f - __bfloat162float(h));
}

// weight layout (element counts)
#define NW_P  (EDIM * DFEAT)
#define NW_Q  (EDIM * EDIM)
#define NW_KV (2 * EDIM * EDIM)
#define NW_O  (EDIM * EDIM)
#define NW_TOTAL (NW_P + NW_Q + NW_KV + NW_O + NW_O)

__device__ __forceinline__ void convert_one_weight(int i, const float* pw, const float* ipw,
                                                   const float* opw, const float* fw) {
    __nv_bfloat16 h, l;
    if (i < NW_P) {
        split_bf16(pw[i], h, l);
        g_wphi[i] = h; g_wplo[i] = l;
    } else if (i < NW_P + NW_Q) {
        int j = i - NW_P;
        split_bf16(ipw[j], h, l);
        g_wqhi[j] = h; g_wqlo[j] = l;
    } else if (i < NW_P + NW_Q + NW_KV) {
        int j = i - NW_P - NW_Q;
        split_bf16(ipw[NW_Q + j], h, l);
        g_wkvhi[j] = h; g_wkvlo[j] = l;
    } else if (i < NW_P + NW_Q + NW_KV + NW_O) {
        int j = i - NW_P - NW_Q - NW_KV;
        split_bf16(opw[j], h, l);
        g_wohi[j] = h; g_wolo[j] = l;
    } else {
        int j = i - NW_P - NW_Q - NW_KV - NW_O;
        split_bf16(fw[j], h, l);
        g_wfhi[j] = h; g_wflo[j] = l;
    }
}

// ------------------------- topk T1: per-slice hist + weight convert ----------
__global__ void topk_hist(const float* __restrict__ scores,
                          const float* __restrict__ pw, const float* __restrict__ ipw,
                          const float* __restrict__ opw, const float* __restrict__ fw) {
    const int b = blockIdx.x >> 3, s = blockIdx.x & 7;
    const float* sp = scores + (size_t)b * NPTS + s * 4096;
    __shared__ unsigned int h[256];
    const int tid = threadIdx.x;
    h[tid] = 0;
    if (tid == 0 && s == 0) g_cnt[b] = 0;
    __syncthreads();
    #pragma unroll
    for (int j = 0; j < 16; j++) {
        unsigned int u = f2u(sp[tid + j * 256]);
        atomicAdd(&h[u >> 24], 1u);
    }
    __syncthreads();
    g_hist[(b * 8 + s) * 256 + tid] = h[tid];
    for (int i = blockIdx.x * 256 + tid; i < NW_TOTAL; i += 128 * 256)
        convert_one_weight(i, pw, ipw, opw, fw);
}

// T2: byte threshold per batch, compact candidates
__global__ void topk_filter(const float* __restrict__ scores) {
    const int b = blockIdx.x >> 3, s = blockIdx.x & 7;
    const int tid = threadIdx.x;
    __shared__ unsigned int h[256];
    __shared__ int sh_b0;
    unsigned int acc8 = 0;
    #pragma unroll
    for (int ss = 0; ss < 8; ss++) acc8 += g_hist[(b * 8 + ss) * 256 + tid];
    h[tid] = acc8;
    __syncthreads();
    if (tid == 0) {
        int acc = 0, byte = 255;
        for (; byte >= 0; byte--) { acc += (int)h[byte]; if (acc >= KSEL) break; }
        sh_b0 = byte;
    }
    __syncthreads();
    const unsigned int thr = (unsigned int)sh_b0 << 24;
    const float* sp = scores + (size_t)b * NPTS + s * 4096;
    #pragma unroll
    for (int j = 0; j < 16; j++) {
        int i = tid + j * 256;
        unsigned int u = f2u(sp[i]);
        if (u >= thr) {
            int p = atomicAdd(&g_cnt[b], 1);
            if (p < CAND_MAX) {
                unsigned int gi = (unsigned int)(s * 4096 + i);
                g_cand[b * CAND_MAX + p] = ((unsigned long long)u << 32) | (unsigned int)(~gi);
            }
        }
    }
}

// T3: sort candidates desc by (value, ~idx)
__global__ void topk_final(int* __restrict__ out_idx) {
    const int b = blockIdx.x;
    const int tid = threadIdx.x;   // 512
    __shared__ unsigned long long sk[CAND_MAX];
    int n = g_cnt[b];
    if (n > CAND_MAX) n = CAND_MAX;
    int n2 = 512;
    while (n2 < n) n2 <<= 1;
    for (int i = tid; i < n2; i += 512)
        sk[i] = (i < n) ? g_cand[b * CAND_MAX + i] : 0ull;
    __syncthreads();
    for (int size = 2; size <= n2; size <<= 1)
        for (int stride = size >> 1; stride >= 1; stride >>= 1) {
            for (int t = tid; t < (n2 >> 1); t += 512) {
                int low = t & (stride - 1);
                int i = ((t - low) << 1) | low;
                int j = i | stride;
                unsigned long long a = sk[i], c = sk[j];
                bool desc = ((i & size) == 0);
                if (desc ? (a < c) : (a > c)) { sk[i] = c; sk[j] = a; }
            }
            __syncthreads();
        }
    if (tid < KSEL)
        out_idx[b * KSEL + tid] = (int)(~(unsigned int)(sk[tid] & 0xFFFFFFFFu));
}

// ------------------------- gather + fp32->hi/lo convert (once per row) -------
__global__ void gather_convert(const float* __restrict__ ppf, const int* __restrict__ idx) {
    const int r = blockIdx.x * 4 + (threadIdx.x >> 6);   // 0..8191
    const int d = (threadIdx.x & 63) * 4;
    const int b = r >> 9;
    const float* src = ppf + ((size_t)b * NPTS + (size_t)idx[r]) * DFEAT;
    float4 f = *(const float4*)(src + d);
    __nv_bfloat16 h0,h1,h2,h3,l0,l1,l2,l3;
    split_bf16(f.x,h0,l0); split_bf16(f.y,h1,l1);
    split_bf16(f.z,h2,l2); split_bf16(f.w,h3,l3);
    size_t o = (size_t)r * DFEAT + d;
    *(__nv_bfloat162*)&g_ahi[o]     = __nv_bfloat162{h0,h1};
    *(__nv_bfloat162*)&g_ahi[o + 2] = __nv_bfloat162{h2,h3};
    *(__nv_bfloat162*)&g_alo[o]     = __nv_bfloat162{l0,l1};
    *(__nv_bfloat162*)&g_alo[o + 2] = __nv_bfloat162{l2,l3};
}

// ------------------------- big GEMM: CTA 128x64, 3 CTAs/SM (proven R12) ------
// C[M, ncout] = (Ahi+Alo)[M,K] @ (Bhi+Blo)[ncout,K]^T + bias
// 8 warps 4(m)x2(n), warp tile 32x32, 48KB smem -> 3 CTAs/SM (24 warps).
// EPI 0: fp32 C.  EPI 1: bf16 hi/lo C (stride EDIM) + fp32 rows (t<16) -> Cfp.
#define BA_HI 0
#define BA_LO 16384
#define BB_HI 32768
#define BB_LO 40960
#define BIG_SMEM 49152

template<int EPI>
__global__ void __launch_bounds__(256, 3)
big_gemm(const __nv_bfloat16* __restrict__ Ahi, const __nv_bfloat16* __restrict__ Alo,
         const __nv_bfloat16* __restrict__ Bhi, const __nv_bfloat16* __restrict__ Blo,
         const float* __restrict__ bias, int K, int ncout,
         float* __restrict__ Cfp, __nv_bfloat16* __restrict__ Chi, __nv_bfloat16* __restrict__ Clo)
{
    extern __shared__ char sm[];
    const uint32_t smb = smem_u32(sm);
    const int tid  = threadIdx.x;
    const int wid  = tid >> 5;
    const int lane = tid & 31;
    const int wm = wid & 3;          // 4 m-warps, 32 rows each
    const int wn = wid >> 2;         // 2 n-warps, 32 cols each
    const int mbase = blockIdx.x * 128;
    const int nbase = blockIdx.y * 64;

    float acc[2][4][4];
    #pragma unroll
    for (int i = 0; i < 2; i++)
        #pragma unroll
        for (int j = 0; j < 4; j++)
            #pragma unroll
            for (int t = 0; t < 4; t++) acc[i][j][t] = 0.f;

    const int arow_l = (lane & 7) + ((lane >> 3) & 1) * 8;
    const int akb_l  = (lane >> 4) * 16;
    const int brow_l = (lane & 7) + ((lane >> 4) & 1) * 8;
    const int bkb_l  = ((lane >> 3) & 1) * 16;

    const int ldrow = tid >> 3;      // 0..31
    const int ldq   = tid & 7;
    const uint32_t ldoff = (uint32_t)(ldq * 16);
    const int nch = K >> 6;

    for (int c = 0; c < nch; c++) {
        __syncthreads();
        #pragma unroll
        for (int p = 0; p < 4; p++) {
            int row = p * 32 + ldrow;
            uint32_t dsto = (uint32_t)(row * 128) + (ldoff ^ (uint32_t)((row & 7) << 4));
            size_t srca = (size_t)(mbase + row) * K + c * 64 + ldq * 8;
            CP_ASYNC16(smb + BA_HI + dsto, Ahi + srca);
            CP_ASYNC16(smb + BA_LO + dsto, Alo + srca);
        }
        #pragma unroll
        for (int p = 0; p < 2; p++) {
            int row = p * 32 + ldrow;
            uint32_t dsto = (uint32_t)(row * 128) + (ldoff ^ (uint32_t)((row & 7) << 4));
            size_t srcb = (size_t)(nbase + row) * K + c * 64 + ldq * 8;
            CP_ASYNC16(smb + BB_HI + dsto, Bhi + srcb);
            CP_ASYNC16(smb + BB_LO + dsto, Blo + srcb);
        }
        CP_COMMIT();
        CP_WAIT(0);
        __syncthreads();

        #pragma unroll
        for (int kk = 0; kk < 4; kk++) {
            uint32_t ah[2][4], al[2][4];
            #pragma unroll
            for (int mt = 0; mt < 2; mt++) {
                int row = wm * 32 + mt * 16 + arow_l;
                uint32_t kb = (uint32_t)(kk * 32 + akb_l) ^ (uint32_t)((row & 7) << 4);
                uint32_t ad = (uint32_t)(row * 128) + kb;
                ldsm4(ah[mt], smb + BA_HI + ad);
                ldsm4(al[mt], smb + BA_LO + ad);
            }
            #pragma unroll
            for (int np = 0; np < 2; np++) {
                int row = wn * 32 + np * 16 + brow_l;
                uint32_t kb = (uint32_t)(kk * 32 + bkb_l) ^ (uint32_t)((row & 7) << 4);
                uint32_t bd = (uint32_t)(row * 128) + kb;
                uint32_t bh[4], bl[4];
                ldsm4(bh, smb + BB_HI + bd);
                ldsm4(bl, smb + BB_LO + bd);
                mma_bf16(acc[0][2*np],   ah[0], bh[0], bh[1]);
                mma_bf16(acc[1][2*np],   ah[1], bh[0], bh[1]);
                mma_bf16(acc[0][2*np+1], ah[0], bh[2], bh[3]);
                mma_bf16(acc[1][2*np+1], ah[1], bh[2], bh[3]);
                mma_bf16(acc[0][2*np],   ah[0], bl[0], bl[1]);
                mma_bf16(acc[1][2*np],   ah[1], bl[0], bl[1]);
                mma_bf16(acc[0][2*np+1], ah[0], bl[2], bl[3]);
                mma_bf16(acc[1][2*np+1], ah[1], bl[2], bl[3]);
                mma_bf16(acc[0][2*np],   al[0], bh[0], bh[1]);
                mma_bf16(acc[1][2*np],   al[1], bh[0], bh[1]);
                mma_bf16(acc[0][2*np+1], al[0], bh[2], bh[3]);
                mma_bf16(acc[1][2*np+1], al[1], bh[2], bh[3]);
            }
        }
    }

    const int rrow = lane >> 2;
    const int rcol = (lane & 3) * 2;
    #pragma unroll
    for (int mt = 0; mt < 2; mt++) {
        #pragma unroll
        for (int nt = 0; nt < 4; nt++) {
            int col = nbase + wn * 32 + nt * 8 + rcol;
            float b0 = bias[col], b1 = bias[col + 1];
            #pragma unroll
            for (int h = 0; h < 2; h++) {
                int r = mbase + wm * 32 + mt * 16 + rrow + h * 8;
                float v0 = acc[mt][nt][2*h]   + b0;
                float v1 = acc[mt][nt][2*h+1] + b1;
                if (EPI == 0) {
                    *(float2*)&Cfp[(size_t)r * ncout + col] = make_float2(v0, v1);
                } else {
                    __nv_bfloat16 h0, h1, l0, l1;
                    split_bf16(v0, h0, l0); split_bf16(v1, h1, l1);
                    size_t o = (size_t)r * EDIM + col;
                    *(__nv_bfloat162*)&Chi[o] = __nv_bfloat162{h0, h1};
                    *(__nv_bfloat162*)&Clo[o] = __nv_bfloat162{l0, l1};
                    int t = r & 511, bb = r >> 9;
                    if (t < TOUT) {
                        size_t oq = (size_t)(bb * TOUT + t) * EDIM + col;
                        *(float2*)&Cfp[oq] = make_float2(v0, v1);
                    }
                }
            }
        }
    }
}

// ------------------------- small-M split-bf16 GEMM (CTA 64x64, 2-stage) -------
#define QA_HI 0
#define QA_LO 8192
#define QB_HI 16384
#define QB_LO 24576
#define QSTG  32768
#define SGEMM_SMEM (2 * QSTG)

template<int EPI, int MODE>
__global__ void __launch_bounds__(256, 2)
small_gemm(const __nv_bfloat16* __restrict__ Ahi, const __nv_bfloat16* __restrict__ Alo,
           const __nv_bfloat16* __restrict__ Bhi, const __nv_bfloat16* __restrict__ Blo,
           const float* __restrict__ bias, const float* __restrict__ yres,
           float* __restrict__ Cout)
{
    extern __shared__ char sm[];
    const uint32_t smb = smem_u32(sm);
    const int tid  = threadIdx.x;
    const int wid  = tid >> 5;
    const int lane = tid & 31;
    const int wm = wid & 1;
    const int wn = wid >> 1;
    const int mbase = blockIdx.x * 64;
    const int nbase = blockIdx.y * 64;

    float acc[2][2][4];
    #pragma unroll
    for (int i = 0; i < 2; i++)
        #pragma unroll
        for (int j = 0; j < 2; j++)
            #pragma unroll
            for (int t = 0; t < 4; t++) acc[i][j][t] = 0.f;

    const int arow_l = (lane & 7) + ((lane >> 3) & 1) * 8;
    const int akb_l  = (lane >> 4) * 16;
    const int brow_l = (lane & 7) + ((lane >> 4) & 1) * 8;
    const int bkb_l  = ((lane >> 3) & 1) * 16;

    const int ldrow = tid >> 3;
    const int ldq   = tid & 7;
    const uint32_t ldoff = (uint32_t)(ldq * 16);

    size_t srcA[2], srcB[2];
    uint32_t dsto[2];
    #pragma unroll
    for (int p = 0; p < 2; p++) {
        int row = p * 32 + ldrow;
        dsto[p] = (uint32_t)(row * 128) + (ldoff ^ (uint32_t)((row & 7) << 4));
        int lr = mbase + row;
        int ar = (MODE == 0) ? lr : ((lr >> 4) * KSEL + (lr & 15));
        srcA[p] = (size_t)ar * EDIM + ldq * 8;
        srcB[p] = (size_t)(nbase + row) * EDIM + ldq * 8;
    }

    #pragma unroll
    for (int p = 0; p < 2; p++) {
        CP_ASYNC16(smb + QA_HI + dsto[p], Ahi + srcA[p]);
        CP_ASYNC16(smb + QA_LO + dsto[p], Alo + srcA[p]);
        CP_ASYNC16(smb + QB_HI + dsto[p], Bhi + srcB[p]);
        CP_ASYNC16(smb + QB_LO + dsto[p], Blo + srcB[p]);
    }
    CP_COMMIT();

    #pragma unroll 1
    for (int c = 0; c < 8; c++) {
        if (c + 1 < 8) {
            const uint32_t sb = smb + ((c + 1) & 1) * QSTG;
            const size_t ko = (size_t)(c + 1) * 64;
            #pragma unroll
            for (int p = 0; p < 2; p++) {
                CP_ASYNC16(sb + QA_HI + dsto[p], Ahi + srcA[p] + ko);
                CP_ASYNC16(sb + QA_LO + dsto[p], Alo + srcA[p] + ko);
                CP_ASYNC16(sb + QB_HI + dsto[p], Bhi + srcB[p] + ko);
                CP_ASYNC16(sb + QB_LO + dsto[p], Blo + srcB[p] + ko);
            }
            CP_COMMIT();
            CP_WAIT(1);
        } else {
            CP_WAIT(0);
        }
        __syncthreads();

        const uint32_t sb = smb + (c & 1) * QSTG;
        #pragma unroll
        for (int kk = 0; kk < 4; kk++) {
            uint32_t ah[2][4], al[2][4];
            #pragma unroll
            for (int mt = 0; mt < 2; mt++) {
                int row = wm * 32 + mt * 16 + arow_l;
                uint32_t kb = (uint32_t)(kk * 32 + akb_l) ^ (uint32_t)((row & 7) << 4);
                uint32_t ad = (uint32_t)(row * 128) + kb;
                ldsm4(ah[mt], sb + QA_HI + ad);
                ldsm4(al[mt], sb + QA_LO + ad);
            }
            {
                int row = wn * 16 + brow_l;
                uint32_t kb = (uint32_t)(kk * 32 + bkb_l) ^ (uint32_t)((row & 7) << 4);
                uint32_t bd = (uint32_t)(row * 128) + kb;
                uint32_t bh[4], bl[4];
                ldsm4(bh, sb + QB_HI + bd);
                ldsm4(bl, sb + QB_LO + bd);
                mma_bf16(acc[0][0], ah[0], bh[0], bh[1]);
                mma_bf16(acc[1][0], ah[1], bh[0], bh[1]);
                mma_bf16(acc[0][1], ah[0], bh[2], bh[3]);
                mma_bf16(acc[1][1], ah[1], bh[2], bh[3]);
                mma_bf16(acc[0][0], ah[0], bl[0], bl[1]);
                mma_bf16(acc[1][0], ah[1], bl[0], bl[1]);
                mma_bf16(acc[0][1], ah[0], bl[2], bl[3]);
                mma_bf16(acc[1][1], ah[1], bl[2], bl[3]);
                mma_bf16(acc[0][0], al[0], bh[0], bh[1]);
                mma_bf16(acc[1][0], al[1], bh[0], bh[1]);
                mma_bf16(acc[0][1], al[0], bh[2], bh[3]);
                mma_bf16(acc[1][1], al[1], bh[2], bh[3]);
            }
        }
        __syncthreads();
    }

    const int rrow = lane >> 2;
    const int rcol = (lane & 3) * 2;
    #pragma unroll
    for (int mt = 0; mt < 2; mt++) {
        #pragma unroll
        for (int nt = 0; nt < 2; nt++) {
            int col = nbase + wn * 16 + nt * 8 + rcol;
            float b0 = bias[col], b1 = bias[col + 1];
            #pragma unroll
            for (int h = 0; h < 2; h++) {
                int r = mbase + wm * 32 + mt * 16 + rrow + h * 8;
                float v0 = acc[mt][nt][2*h]   + b0;
                float v1 = acc[mt][nt][2*h+1] + b1;
                size_t o = (size_t)r * EDIM + col;
                if (EPI == 0) {
                    *(float2*)&Cout[o] = make_float2(v0, v1);
                } else {
                    float g0 = 0.5f * v0 * (1.f + erff(v0 * 0.70710678118654752f));
                    float g1 = 0.5f * v1 * (1.f + erff(v1 * 0.70710678118654752f));
                    float2 yr = *(const float2*)&yres[o];
                    *(float2*)&Cout[o] = make_float2(yr.x + g0, yr.y + g1);
                }
            }
        }
    }
}

// ------------------------- attention (256 threads per (b,h)) ------------------
#define ATTN_SMEM ((16*64 + 16*512 + 128*65) * 4)

__global__ void __launch_bounds__(256)
attn_kernel(const float* __restrict__ qb, const float* __restrict__ kv,
            __nv_bfloat16* __restrict__ ohi, __nv_bfloat16* __restrict__ olo)
{
    extern __shared__ float smf[];
    float* s_q  = smf;
    float* s_l  = smf + 16 * 64;
    float* s_kv = smf + 16 * 64 + 16 * 512;
    const int b = blockIdx.x >> 3, h = blockIdx.x & 7;
    const int tid = threadIdx.x;            // 256

    const float* qbase = qb + ((size_t)b * TOUT) * EDIM + h * DH;
    for (int i = tid; i < 16 * 64; i += 256) {
        int t = i >> 6, d = i & 63;
        s_q[i] = qbase[(size_t)t * EDIM + d];
    }
    const float scale = 0.125f;

    for (int c = 0; c < 4; c++) {
        const float* kbase = kv + ((size_t)(b * KSEL + c * 128)) * 1024 + h * DH;
        __syncthreads();
        for (int i = tid; i < 128 * 64; i += 256) {
            int j = i >> 6, d = i & 63;
            s_kv[j * 65 + d] = kbase[(size_t)j * 1024 + d];
        }
        __syncthreads();
        {
            int j = tid & 127, half = tid >> 7;
            float acc[8];
            #pragma unroll
            for (int t = 0; t < 8; t++) acc[t] = 0.f;
            for (int d = 0; d < 64; d++) {
                float kd = s_kv[j * 65 + d];
                #pragma unroll
                for (int t = 0; t < 8; t++) acc[t] += s_q[(half * 8 + t) * 64 + d] * kd;
            }
            #pragma unroll
            for (int t = 0; t < 8; t++)
                s_l[(half * 8 + t) * 512 + c * 128 + j] = acc[t] * scale;
        }
    }
    __syncthreads();

    {
        int row = tid >> 4, l = tid & 15;
        float* lr = s_l + row * 512;
        float m = -1e30f;
        for (int j = l; j < 512; j += 16) m = fmaxf(m, lr[j]);
        for (int o = 8; o >= 1; o >>= 1) m = fmaxf(m, __shfl_xor_sync(0xffffffffu, m, o));
        float sum = 0.f;
        for (int j = l; j < 512; j += 16) { float e = expf(lr[j] - m); lr[j] = e; sum += e; }
        for (int o = 8; o >= 1; o >>= 1) sum += __shfl_xor_sync(0xffffffffu, sum, o);
        float inv = 1.f / sum;
        for (int j = l; j < 512; j += 16) lr[j] *= inv;
    }

    {
        int d = tid & 63, tg = tid >> 6;
        float acc[4];
        #pragma unroll
        for (int t = 0; t < 4; t++) acc[t] = 0.f;
        for (int c = 0; c < 4; c++) {
            const float* vbase = kv + ((size_t)(b * KSEL + c * 128)) * 1024 + 512 + h * DH;
            __syncthreads();
            for (int i = tid; i < 128 * 64; i += 256) {
                int j = i >> 6, dd = i & 63;
                s_kv[j * 65 + dd] = vbase[(size_t)j * 1024 + dd];
            }
            __syncthreads();
            for (int j = 0; j < 128; j++) {
                float vv = s_kv[j * 65 + d];
                #pragma unroll
                for (int t = 0; t < 4; t++)
                    acc[t] += s_l[(tg * 4 + t) * 512 + c * 128 + j] * vv;
            }
        }
        const size_t obase = ((size_t)b * TOUT) * EDIM + h * DH + d;
        #pragma unroll
        for (int t = 0; t < 4; t++) {
            __nv_bfloat16 hh, ll;
            split_bf16(acc[t], hh, ll);
            ohi[obase + (size_t)(tg * 4 + t) * EDIM] = hh;
            olo[obase + (size_t)(tg * 4 + t) * EDIM] = ll;
        }
    }
}

// ------------------------- residual + layernorm ------------------------------
__global__ void ln_kernel(const float* __restrict__ xq, const float* __restrict__ o2,
                          const float* __restrict__ g, const float* __restrict__ be,
                          float* __restrict__ y,
                          __nv_bfloat16* __restrict__ yhi, __nv_bfloat16* __restrict__ ylo)
{
    const int r = blockIdx.x;
    const float* xr = xq + (size_t)r * EDIM;
    const float* orow = o2 + (size_t)r * EDIM;
    const int tid = threadIdx.x;
    float v0 = xr[tid] + orow[tid];
    float v1 = xr[tid + 256] + orow[tid + 256];
    float s = v0 + v1, sq = v0 * v0 + v1 * v1;
    for (int o = 16; o >= 1; o >>= 1) {
        s  += __shfl_xor_sync(0xffffffffu, s, o);
        sq += __shfl_xor_sync(0xffffffffu, sq, o);
    }
    __shared__ float ss[8], ssq[8];
    __shared__ float mu, rstd;
    int w = tid >> 5;
    if ((tid & 31) == 0) { ss[w] = s; ssq[w] = sq; }
    __syncthreads();
    if (tid == 0) {
        float S = 0.f, SQ = 0.f;
        for (int i = 0; i < 8; i++) { S += ss[i]; SQ += ssq[i]; }
        float m = S / 512.f;
        float var = SQ / 512.f - m * m;
        mu = m; rstd = rsqrtf(var + 1e-5f);
    }
    __syncthreads();
    float y0 = (v0 - mu) * rstd * g[tid]       + be[tid];
    float y1 = (v1 - mu) * rstd * g[tid + 256] + be[tid + 256];
    y[(size_t)r * EDIM + tid]       = y0;
    y[(size_t)r * EDIM + tid + 256] = y1;
    __nv_bfloat16 h0, l0, h1, l1;
    split_bf16(y0, h0, l0); split_bf16(y1, h1, l1);
    yhi[(size_t)r * EDIM + tid]       = h0;
    ylo[(size_t)r * EDIM + tid]       = l0;
    yhi[(size_t)r * EDIM + tid + 256] = h1;
    ylo[(size_t)r * EDIM + tid + 256] = l1;
}

// ------------------------- launcher ------------------------------------------
extern "C" void kernel_launch(void* const* d_in, const int* in_sizes, int n_in,
                              void* d_out, int out_size)
{
    const float* ppf = (const float*)d_in[0];
    const float* sc  = (const float*)d_in[1];
    const float* pw  = (const float*)d_in[2];
    const float* pb  = (const float*)d_in[3];
    const float* ipw = (const float*)d_in[4];
    const float* ipb = (const float*)d_in[5];
    const float* opw = (const float*)d_in[6];
    const float* opb = (const float*)d_in[7];
    const float* lng = (const float*)d_in[8];
    const float* lnb = (const float*)d_in[9];
    const float* fw  = (const float*)d_in[10];
    const float* fb  = (const float*)d_in[11];
    float* out = (float*)d_out;

    int* idx;
    __nv_bfloat16 *ahi, *alo, *wphi, *wplo, *wqhi, *wqlo, *wkvhi, *wkvlo;
    __nv_bfloat16 *wohi, *wolo, *wfhi, *wflo, *xhi, *xlo, *ohi, *olo, *yhi, *ylo;
    float *kv, *xq, *q, *o2, *y;
    cudaGetSymbolAddress((void**)&idx,   g_idx);
    cudaGetSymbolAddress((void**)&ahi,   g_ahi);
    cudaGetSymbolAddress((void**)&alo,   g_alo);
    cudaGetSymbolAddress((void**)&wphi,  g_wphi);
    cudaGetSymbolAddress((void**)&wplo,  g_wplo);
    cudaGetSymbolAddress((void**)&wqhi,  g_wqhi);
    cudaGetSymbolAddress((void**)&wqlo,  g_wqlo);
    cudaGetSymbolAddress((void**)&wkvhi, g_wkvhi);
    cudaGetSymbolAddress((void**)&wkvlo, g_wkvlo);
    cudaGetSymbolAddress((void**)&wohi,  g_wohi);
    cudaGetSymbolAddress((void**)&wolo,  g_wolo);
    cudaGetSymbolAddress((void**)&wfhi,  g_wfhi);
    cudaGetSymbolAddress((void**)&wflo,  g_wflo);
    cudaGetSymbolAddress((void**)&xhi,   g_xhi);
    cudaGetSymbolAddress((void**)&xlo,   g_xlo);
    cudaGetSymbolAddress((void**)&kv,    g_kv);
    cudaGetSymbolAddress((void**)&xq,    g_xq);
    cudaGetSymbolAddress((void**)&q,     g_q);
    cudaGetSymbolAddress((void**)&ohi,   g_ohi);
    cudaGetSymbolAddress((void**)&olo,   g_olo);
    cudaGetSymbolAddress((void**)&o2,    g_o2);
    cudaGetSymbolAddress((void**)&y,     g_y);
    cudaGetSymbolAddress((void**)&yhi,   g_yhi);
    cudaGetSymbolAddress((void**)&ylo,   g_ylo);

    cudaFuncSetAttribute(big_gemm<0>,     cudaFuncAttributeMaxDynamicSharedMemorySize, BIG_SMEM);
    cudaFuncSetAttribute(big_gemm<1>,     cudaFuncAttributeMaxDynamicSharedMemorySize, BIG_SMEM);
    cudaFuncSetAttribute(small_gemm<0,1>, cudaFuncAttributeMaxDynamicSharedMemorySize, SGEMM_SMEM);
    cudaFuncSetAttribute(small_gemm<0,0>, cudaFuncAttributeMaxDynamicSharedMemorySize, SGEMM_SMEM);
    cudaFuncSetAttribute(small_gemm<2,0>, cudaFuncAttributeMaxDynamicSharedMemorySize, SGEMM_SMEM);
    cudaFuncSetAttribute(attn_kernel,     cudaFuncAttributeMaxDynamicSharedMemorySize, ATTN_SMEM);

    // 1) topk (hist also converts weights + zeroes g_cnt)
    topk_hist<<<128, 256>>>(sc, pw, ipw, opw, fw);
    topk_filter<<<128, 256>>>(sc);
    topk_final<<<16, 512>>>(idx);

    // 1b) gather + convert (once per selected row)
    gather_convert<<<2048, 256>>>(ppf, idx);

    // 2) x = A @ proj_w^T + pb  (128x64 tiles, 3 CTAs/SM, K=256)
    big_gemm<1><<<dim3(64, 8), 256, BIG_SMEM>>>(ahi, alo, wphi, wplo, pb, DFEAT, EDIM,
                                                xq, xhi, xlo);

    // 3) kv = x @ Wkv^T + b  (128x64 tiles, 3 CTAs/SM, K=512, N=1024)
    big_gemm<0><<<dim3(64, 16), 256, BIG_SMEM>>>(xhi, xlo, wkvhi, wkvlo, ipb + EDIM,
                                                 EDIM, 1024, kv, nullptr, nullptr);

    // 4) q = x[:, :16] @ Wq^T + b
    small_gemm<0,1><<<dim3(4, 8), 256, SGEMM_SMEM>>>(xhi, xlo, wqhi, wqlo, ipb, nullptr, q);

    // 5) attention -> o (bf16 hi/lo)
    attn_kernel<<<128, 256, ATTN_SMEM>>>(q, kv, ohi, olo);

    // 6) out_proj
    small_gemm<0,0><<<dim3(4, 8), 256, SGEMM_SMEM>>>(ohi, olo, wohi, wolo, opb, nullptr, o2);

    // 7) residual + layernorm
    ln_kernel<<<256, 256>>>(xq, o2, lng, lnb, y, yhi, ylo);

    // 8) FFN GEMM + fused gelu + residual -> out
    small_gemm<2,0><<<dim3(4, 8), 256, SGEMM_SMEM>>>(yhi, ylo, wfhi, wflo, fb, y, out);
}

// round 16
// speedup vs baseline: 1.0029x; 1.0029x over previous
#include <cuda_runtime.h>
#include <cuda_bf16.h>
#include <cstdint>

#define B_SZ   16
#define NPTS   32768
#define DFEAT  256
#define EDIM   512
#define KSEL   512
#define HEADS  8
#define DH     64
#define TOUT   16
#define CAND_MAX 4096

// ------------------------- scratch (device globals, no allocs) ----------------
__device__ int   g_idx[B_SZ * KSEL];
__device__ unsigned int g_hist[B_SZ * 8 * 256];
__device__ int   g_cnt[B_SZ];
__device__ unsigned long long g_cand[B_SZ * CAND_MAX];
__device__ __nv_bfloat16 g_wphi[EDIM * DFEAT];
__device__ __nv_bfloat16 g_wplo[EDIM * DFEAT];
__device__ __nv_bfloat16 g_wqhi[EDIM * EDIM];
__device__ __nv_bfloat16 g_wqlo[EDIM * EDIM];
__device__ __nv_bfloat16 g_wkvhi[2 * EDIM * EDIM];
__device__ __nv_bfloat16 g_wkvlo[2 * EDIM * EDIM];
__device__ __nv_bfloat16 g_wohi[EDIM * EDIM];
__device__ __nv_bfloat16 g_wolo[EDIM * EDIM];
__device__ __nv_bfloat16 g_wfhi[EDIM * EDIM];
__device__ __nv_bfloat16 g_wflo[EDIM * EDIM];
__device__ __nv_bfloat16 g_xhi[B_SZ * KSEL * EDIM];
__device__ __nv_bfloat16 g_xlo[B_SZ * KSEL * EDIM];
__device__ float g_kv[B_SZ * KSEL * 2 * EDIM];   // row stride 1024: [k | v]
__device__ float g_xq[B_SZ * TOUT * EDIM];
__device__ float g_q [B_SZ * TOUT * EDIM];
__device__ __nv_bfloat16 g_ohi[B_SZ * TOUT * EDIM];
__device__ __nv_bfloat16 g_olo[B_SZ * TOUT * EDIM];
__device__ float g_o2[B_SZ * TOUT * EDIM];
__device__ float g_y [B_SZ * TOUT * EDIM];
__device__ __nv_bfloat16 g_yhi[B_SZ * TOUT * EDIM];
__device__ __nv_bfloat16 g_ylo[B_SZ * TOUT * EDIM];

// ------------------------- helpers -------------------------------------------
__device__ __forceinline__ uint32_t smem_u32(const void* p) {
    uint32_t a;
    asm("{ .reg .u64 t; cvta.to.shared.u64 t, %1; cvt.u32.u64 %0, t; }" : "=r"(a) : "l"(p));
    return a;
}
__device__ __forceinline__ void ldsm4(uint32_t (&r)[4], uint32_t addr) {
    asm volatile("ldmatrix.sync.aligned.m8n8.x4.shared.b16 {%0,%1,%2,%3}, [%4];"
                 : "=r"(r[0]), "=r"(r[1]), "=r"(r[2]), "=r"(r[3]) : "r"(addr));
}
__device__ __forceinline__ void mma_bf16(float (&d)[4], const uint32_t (&a)[4],
                                         uint32_t b0, uint32_t b1) {
    asm volatile("mma.sync.aligned.m16n8k16.row.col.f32.bf16.bf16.f32 "
                 "{%0,%1,%2,%3}, {%4,%5,%6,%7}, {%8,%9}, {%0,%1,%2,%3};"
                 : "+f"(d[0]), "+f"(d[1]), "+f"(d[2]), "+f"(d[3])
                 : "r"(a[0]), "r"(a[1]), "r"(a[2]), "r"(a[3]), "r"(b0), "r"(b1));
}
#define CP_ASYNC16(dst, src) \
    asm volatile("cp.async.cg.shared.global [%0], [%1], 16;" :: "r"(dst), "l"(src))
#define CP_COMMIT() asm volatile("cp.async.commit_group;")
#define CP_WAIT(n)  asm volatile("cp.async.wait_group %0;" :: "n"(n))

__device__ __forceinline__ unsigned int f2u(float f) {
    unsigned int u = __float_as_uint(f);
    return (u & 0x80000000u) ? ~u : (u | 0x80000000u);
}
__device__ __forceinline__ void split_bf16(float f, __nv_bfloat16& h, __nv_bfloat16& l) {
    h = __float2bfloat16_rn(f);
    l = __float2bfloat16_rn(f - __bfloat162float(h));
}

// weight layout (element counts)
#define NW_P  (EDIM * DFEAT)
#define NW_Q  (EDIM * EDIM)
#define NW_KV (2 * EDIM * EDIM)
#define NW_O  (EDIM * EDIM)
#define NW_TOTAL (NW_P + NW_Q + NW_KV + NW_O + NW_O)

__device__ __forceinline__ void convert_one_weight(int i, const float* pw, const float* ipw,
                                                   const float* opw, const float* fw) {
    __nv_bfloat16 h, l;
    if (i < NW_P) {
        split_bf16(pw[i], h, l);
        g_wphi[i] = h; g_wplo[i] = l;
    } else if (i < NW_P + NW_Q) {
        int j = i - NW_P;
        split_bf16(ipw[j], h, l);
        g_wqhi[j] = h; g_wqlo[j] = l;
    } else if (i < NW_P + NW_Q + NW_KV) {
        int j = i - NW_P - NW_Q;
        split_bf16(ipw[NW_Q + j], h, l);
        g_wkvhi[j] = h; g_wkvlo[j] = l;
    } else if (i < NW_P + NW_Q + NW_KV + NW_O) {
        int j = i - NW_P - NW_Q - NW_KV;
        split_bf16(opw[j], h, l);
        g_wohi[j] = h; g_wolo[j] = l;
    } else {
        int j = i - NW_P - NW_Q - NW_KV - NW_O;
        split_bf16(fw[j], h, l);
        g_wfhi[j] = h; g_wflo[j] = l;
    }
}

// ------------------------- topk T1: per-slice hist + weight convert ----------
__global__ void topk_hist(const float* __restrict__ scores,
                          const float* __restrict__ pw, const float* __restrict__ ipw,
                          const float* __restrict__ opw, const float* __restrict__ fw) {
    const int b = blockIdx.x >> 3, s = blockIdx.x & 7;
    const float* sp = scores + (size_t)b * NPTS + s * 4096;
    __shared__ unsigned int h[256];
    const int tid = threadIdx.x;
    h[tid] = 0;
    if (tid == 0 && s == 0) g_cnt[b] = 0;
    __syncthreads();
    #pragma unroll
    for (int j = 0; j < 16; j++) {
        unsigned int u = f2u(sp[tid + j * 256]);
        atomicAdd(&h[u >> 24], 1u);
    }
    __syncthreads();
    g_hist[(b * 8 + s) * 256 + tid] = h[tid];
    for (int i = blockIdx.x * 256 + tid; i < NW_TOTAL; i += 128 * 256)
        convert_one_weight(i, pw, ipw, opw, fw);
}

// T2: byte threshold per batch, compact candidates
__global__ void topk_filter(const float* __restrict__ scores) {
    const int b = blockIdx.x >> 3, s = blockIdx.x & 7;
    const int tid = threadIdx.x;
    __shared__ unsigned int h[256];
    __shared__ int sh_b0;
    unsigned int acc8 = 0;
    #pragma unroll
    for (int ss = 0; ss < 8; ss++) acc8 += g_hist[(b * 8 + ss) * 256 + tid];
    h[tid] = acc8;
    __syncthreads();
    if (tid == 0) {
        int acc = 0, byte = 255;
        for (; byte >= 0; byte--) { acc += (int)h[byte]; if (acc >= KSEL) break; }
        sh_b0 = byte;
    }
    __syncthreads();
    const unsigned int thr = (unsigned int)sh_b0 << 24;
    const float* sp = scores + (size_t)b * NPTS + s * 4096;
    #pragma unroll
    for (int j = 0; j < 16; j++) {
        int i = tid + j * 256;
        unsigned int u = f2u(sp[i]);
        if (u >= thr) {
            int p = atomicAdd(&g_cnt[b], 1);
            if (p < CAND_MAX) {
                unsigned int gi = (unsigned int)(s * 4096 + i);
                g_cand[b * CAND_MAX + p] = ((unsigned long long)u << 32) | (unsigned int)(~gi);
            }
        }
    }
}

// T3: sort candidates desc by (value, ~idx)
__global__ void topk_final(int* __restrict__ out_idx) {
    const int b = blockIdx.x;
    const int tid = threadIdx.x;   // 512
    __shared__ unsigned long long sk[CAND_MAX];
    int n = g_cnt[b];
    if (n > CAND_MAX) n = CAND_MAX;
    int n2 = 512;
    while (n2 < n) n2 <<= 1;
    for (int i = tid; i < n2; i += 512)
        sk[i] = (i < n) ? g_cand[b * CAND_MAX + i] : 0ull;
    __syncthreads();
    for (int size = 2; size <= n2; size <<= 1)
        for (int stride = size >> 1; stride >= 1; stride >>= 1) {
            for (int t = tid; t < (n2 >> 1); t += 512) {
                int low = t & (stride - 1);
                int i = ((t - low) << 1) | low;
                int j = i | stride;
                unsigned long long a = sk[i], c = sk[j];
                bool desc = ((i & size) == 0);
                if (desc ? (a < c) : (a > c)) { sk[i] = c; sk[j] = a; }
            }
            __syncthreads();
        }
    if (tid < KSEL)
        out_idx[b * KSEL + tid] = (int)(~(unsigned int)(sk[tid] & 0xFFFFFFFFu));
}

// ------------------------- gather split-bf16 GEMM (CTA 128x128, 256 thr) -----
// R12-proven: fp32 staging in SMEM, 2 CTAs/SM.
#define GTH_SMEM 98304

__global__ void __launch_bounds__(256, 2)
gather_gemm(const __nv_bfloat16* __restrict__ Bhi, const __nv_bfloat16* __restrict__ Blo,
            const float* __restrict__ bias,
            float* __restrict__ Cfp, __nv_bfloat16* __restrict__ Chi, __nv_bfloat16* __restrict__ Clo,
            const float* __restrict__ Afp, const int* __restrict__ idxp)
{
    extern __shared__ char sm[];
    const uint32_t smb = smem_u32(sm);
    const uint32_t AF32 = 0;
    const uint32_t AHI = 32768u;
    const uint32_t ALO = AHI + 16384u;
    const uint32_t BHI = ALO + 16384u;
    const uint32_t BLO = BHI + 16384u;
    const int K = DFEAT;

    const int tid  = threadIdx.x;
    const int wid  = tid >> 5;
    const int lane = tid & 31;
    const int wm = wid & 3;
    const int wn = wid >> 2;
    const int mbase = blockIdx.x * 128;
    const int nbase = blockIdx.y * 128;

    float acc[2][8][4];
    #pragma unroll
    for (int i = 0; i < 2; i++)
        #pragma unroll
        for (int j = 0; j < 8; j++)
            #pragma unroll
            for (int t = 0; t < 4; t++) acc[i][j][t] = 0.f;

    const int arow_l = (lane & 7) + ((lane >> 3) & 1) * 8;
    const int akb_l  = (lane >> 4) * 16;
    const int brow_l = (lane & 7) + ((lane >> 4) & 1) * 8;
    const int bkb_l  = ((lane >> 3) & 1) * 16;

    const int ldrow = tid >> 3;
    const int ldq   = tid & 7;
    const uint32_t ldoff = (uint32_t)(ldq * 16);

    const float* aptr[8];
    #pragma unroll
    for (int p = 0; p < 8; p++) {
        int row = p * 16 + (tid >> 4);
        int lr = mbase + row;
        int bb = lr >> 9;
        aptr[p] = Afp + ((size_t)bb * NPTS + (size_t)idxp[lr]) * DFEAT + (tid & 15) * 4;
    }

    for (int c = 0; c < 4; c++) {
        __syncthreads();
        {
            const uint32_t aq16 = (uint32_t)((tid & 15) * 16);
            #pragma unroll
            for (int p = 0; p < 8; p++) {
                int row = p * 16 + (tid >> 4);
                CP_ASYNC16(smb + AF32 + (uint32_t)(row * 256) + aq16, aptr[p] + c * 64);
            }
        }
        #pragma unroll
        for (int p = 0; p < 4; p++) {
            int row = p * 32 + ldrow;
            uint32_t dsto = (uint32_t)(row * 128) + (ldoff ^ (uint32_t)((row & 7) << 4));
            size_t srcb = (size_t)(nbase + row) * K + c * 64 + ldq * 8;
            CP_ASYNC16(smb + BHI + dsto, Bhi + srcb);
            CP_ASYNC16(smb + BLO + dsto, Blo + srcb);
        }
        CP_COMMIT();
        CP_WAIT(0);
        __syncthreads();

        #pragma unroll
        for (int it = 0; it < 8; it++) {
            int f4 = tid + it * 256;
            int row = f4 >> 4, c4 = f4 & 15;
            float4 v = *(const float4*)(sm + AF32 + (size_t)f4 * 16);
            __nv_bfloat16 h0,h1,h2,h3,l0,l1,l2,l3;
            split_bf16(v.x,h0,l0); split_bf16(v.y,h1,l1);
            split_bf16(v.z,h2,l2); split_bf16(v.w,h3,l3);
            uint32_t off = (uint32_t)(row * 128) + (uint32_t)((c4 * 8) ^ ((row & 7) << 4));
            *(__nv_bfloat162*)(sm + AHI + off)     = __nv_bfloat162{h0, h1};
            *(__nv_bfloat162*)(sm + AHI + off + 4) = __nv_bfloat162{h2, h3};
            *(__nv_bfloat162*)(sm + ALO + off)     = __nv_bfloat162{l0, l1};
            *(__nv_bfloat162*)(sm + ALO + off + 4) = __nv_bfloat162{l2, l3};
        }
        __syncthreads();

        #pragma unroll
        for (int kk = 0; kk < 4; kk++) {
            uint32_t ah[2][4], al[2][4];
            #pragma unroll
            for (int mt = 0; mt < 2; mt++) {
                int row = wm * 32 + mt * 16 + arow_l;
                uint32_t kb = (uint32_t)(kk * 32 + akb_l) ^ (uint32_t)((row & 7) << 4);
                uint32_t ad = (uint32_t)(row * 128) + kb;
                ldsm4(ah[mt], smb + AHI + ad);
                ldsm4(al[mt], smb + ALO + ad);
            }
            #pragma unroll
            for (int np = 0; np < 4; np++) {
                int row = wn * 64 + np * 16 + brow_l;
                uint32_t kb = (uint32_t)(kk * 32 + bkb_l) ^ (uint32_t)((row & 7) << 4);
                uint32_t bd = (uint32_t)(row * 128) + kb;
                uint32_t bh[4], bl[4];
                ldsm4(bh, smb + BHI + bd);
                ldsm4(bl, smb + BLO + bd);
                mma_bf16(acc[0][2*np],   ah[0], bh[0], bh[1]);
                mma_bf16(acc[1][2*np],   ah[1], bh[0], bh[1]);
                mma_bf16(acc[0][2*np+1], ah[0], bh[2], bh[3]);
                mma_bf16(acc[1][2*np+1], ah[1], bh[2], bh[3]);
                mma_bf16(acc[0][2*np],   ah[0], bl[0], bl[1]);
                mma_bf16(acc[1][2*np],   ah[1], bl[0], bl[1]);
                mma_bf16(acc[0][2*np+1], ah[0], bl[2], bl[3]);
                mma_bf16(acc[1][2*np+1], ah[1], bl[2], bl[3]);
                mma_bf16(acc[0][2*np],   al[0], bh[0], bh[1]);
                mma_bf16(acc[1][2*np],   al[1], bh[0], bh[1]);
                mma_bf16(acc[0][2*np+1], al[0], bh[2], bh[3]);
                mma_bf16(acc[1][2*np+1], al[1], bh[2], bh[3]);
            }
        }
    }

    const int rrow = lane >> 2;
    const int rcol = (lane & 3) * 2;
    #pragma unroll
    for (int mt = 0; mt < 2; mt++) {
        #pragma unroll
        for (int nt = 0; nt < 8; nt++) {
            int col = nbase + wn * 64 + nt * 8 + rcol;
            float b0 = bias[col], b1 = bias[col + 1];
            #pragma unroll
            for (int h = 0; h < 2; h++) {
                int r = mbase + wm * 32 + mt * 16 + rrow + h * 8;
                float v0 = acc[mt][nt][2*h]   + b0;
                float v1 = acc[mt][nt][2*h+1] + b1;
                __nv_bfloat16 h0, h1, l0, l1;
                split_bf16(v0, h0, l0); split_bf16(v1, h1, l1);
                size_t o = (size_t)r * EDIM + col;
                *(__nv_bfloat162*)&Chi[o] = __nv_bfloat162{h0, h1};
                *(__nv_bfloat162*)&Clo[o] = __nv_bfloat162{l0, l1};
                int t = r & 511, bb = r >> 9;
                if (t < TOUT) {
                    size_t oq = (size_t)(bb * TOUT + t) * EDIM + col;
                    *(float2*)&Cfp[oq] = make_float2(v0, v1);
                }
            }
        }
    }
}

// ------------------------- KV GEMM: CTA 128x64, 512 threads, 2 CTAs/SM -------
// 16 warps as 8(m)x2(n), warp tile 16x32, acc 16 regs -> ~56 regs/thread.
// 48KB smem -> 2 CTAs/SM = 32 warps/SM (next step on the occupancy curve).
#define KVA_HI 0
#define KVA_LO 16384
#define KVB_HI 32768
#define KVB_LO 40960
#define KV_SMEM 49152

__global__ void __launch_bounds__(512, 2)
kv_gemm(const __nv_bfloat16* __restrict__ Ahi, const __nv_bfloat16* __restrict__ Alo,
        const __nv_bfloat16* __restrict__ Bhi, const __nv_bfloat16* __restrict__ Blo,
        const float* __restrict__ bias, float* __restrict__ C)
{
    extern __shared__ char sm[];
    const uint32_t smb = smem_u32(sm);
    const int tid  = threadIdx.x;
    const int wid  = tid >> 5;
    const int lane = tid & 31;
    const int wm = wid & 7;          // 8 m-warps, 16 rows each
    const int wn = wid >> 3;         // 2 n-warps, 32 cols each
    const int mbase = blockIdx.x * 128;
    const int nbase = blockIdx.y * 64;

    float acc[4][4];
    #pragma unroll
    for (int j = 0; j < 4; j++)
        #pragma unroll
        for (int t = 0; t < 4; t++) acc[j][t] = 0.f;

    const int arow_l = (lane & 7) + ((lane >> 3) & 1) * 8;
    const int akb_l  = (lane >> 4) * 16;
    const int brow_l = (lane & 7) + ((lane >> 4) & 1) * 8;
    const int bkb_l  = ((lane >> 3) & 1) * 16;

    const int ldrow = tid >> 3;      // 0..63
    const int ldq   = tid & 7;
    const uint32_t ldoff = (uint32_t)(ldq * 16);

    for (int c = 0; c < 8; c++) {
        __syncthreads();
        // A: 128 rows (2 passes of 64)
        #pragma unroll
        for (int p = 0; p < 2; p++) {
            int row = p * 64 + ldrow;
            uint32_t dsto = (uint32_t)(row * 128) + (ldoff ^ (uint32_t)((row & 7) << 4));
            size_t srca = (size_t)(mbase + row) * EDIM + c * 64 + ldq * 8;
            CP_ASYNC16(smb + KVA_HI + dsto, Ahi + srca);
            CP_ASYNC16(smb + KVA_LO + dsto, Alo + srca);
        }
        // B: 64 rows (1 pass)
        {
            int row = ldrow;
            uint32_t dsto = (uint32_t)(row * 128) + (ldoff ^ (uint32_t)((row & 7) << 4));
            size_t srcb = (size_t)(nbase + row) * EDIM + c * 64 + ldq * 8;
            CP_ASYNC16(smb + KVB_HI + dsto, Bhi + srcb);
            CP_ASYNC16(smb + KVB_LO + dsto, Blo + srcb);
        }
        CP_COMMIT();
        CP_WAIT(0);
        __syncthreads();

        #pragma unroll
        for (int kk = 0; kk < 4; kk++) {
            uint32_t ah[4], al[4];
            {
                int row = wm * 16 + arow_l;
                uint32_t kb = (uint32_t)(kk * 32 + akb_l) ^ (uint32_t)((row & 7) << 4);
                uint32_t ad = (uint32_t)(row * 128) + kb;
                ldsm4(ah, smb + KVA_HI + ad);
                ldsm4(al, smb + KVA_LO + ad);
            }
            uint32_t bh0[4], bl0[4], bh1[4], bl1[4];
            {
                int row = wn * 32 + brow_l;
                uint32_t kb = (uint32_t)(kk * 32 + bkb_l) ^ (uint32_t)((row & 7) << 4);
                ldsm4(bh0, smb + KVB_HI + (uint32_t)(row * 128) + kb);
                ldsm4(bl0, smb + KVB_LO + (uint32_t)(row * 128) + kb);
                int row2 = wn * 32 + 16 + brow_l;
                uint32_t kb2 = (uint32_t)(kk * 32 + bkb_l) ^ (uint32_t)((row2 & 7) << 4);
                ldsm4(bh1, smb + KVB_HI + (uint32_t)(row2 * 128) + kb2);
                ldsm4(bl1, smb + KVB_LO + (uint32_t)(row2 * 128) + kb2);
            }
            // product-major across 4 accumulators (distance 4); per-acc order hh->hl->lh
            mma_bf16(acc[0], ah, bh0[0], bh0[1]);
            mma_bf16(acc[1], ah, bh0[2], bh0[3]);
            mma_bf16(acc[2], ah, bh1[0], bh1[1]);
            mma_bf16(acc[3], ah, bh1[2], bh1[3]);
            mma_bf16(acc[0], ah, bl0[0], bl0[1]);
            mma_bf16(acc[1], ah, bl0[2], bl0[3]);
            mma_bf16(acc[2], ah, bl1[0], bl1[1]);
            mma_bf16(acc[3], ah, bl1[2], bl1[3]);
            mma_bf16(acc[0], al, bh0[0], bh0[1]);
            mma_bf16(acc[1], al, bh0[2], bh0[3]);
            mma_bf16(acc[2], al, bh1[0], bh1[1]);
            mma_bf16(acc[3], al, bh1[2], bh1[3]);
        }
    }

    const int rrow = lane >> 2;
    const int rcol = (lane & 3) * 2;
    #pragma unroll
    for (int nt = 0; nt < 4; nt++) {
        int col = nbase + wn * 32 + nt * 8 + rcol;
        float b0 = bias[col], b1 = bias[col + 1];
        #pragma unroll
        for (int h = 0; h < 2; h++) {
            int r = mbase + wm * 16 + rrow + h * 8;
            float v0 = acc[nt][2*h]   + b0;
            float v1 = acc[nt][2*h+1] + b1;
            *(float2*)&C[(size_t)r * 1024 + col] = make_float2(v0, v1);
        }
    }
}

// ------------------------- small-M split-bf16 GEMM (CTA 64x64, 2-stage) -------
#define QA_HI 0
#define QA_LO 8192
#define QB_HI 16384
#define QB_LO 24576
#define QSTG  32768
#define SGEMM_SMEM (2 * QSTG)

template<int EPI, int MODE>
__global__ void __launch_bounds__(256, 2)
small_gemm(const __nv_bfloat16* __restrict__ Ahi, const __nv_bfloat16* __restrict__ Alo,
           const __nv_bfloat16* __restrict__ Bhi, const __nv_bfloat16* __restrict__ Blo,
           const float* __restrict__ bias, const float* __restrict__ yres,
           float* __restrict__ Cout)
{
    extern __shared__ char sm[];
    const uint32_t smb = smem_u32(sm);
    const int tid  = threadIdx.x;
    const int wid  = tid >> 5;
    const int lane = tid & 31;
    const int wm = wid & 1;
    const int wn = wid >> 1;
    const int mbase = blockIdx.x * 64;
    const int nbase = blockIdx.y * 64;

    float acc[2][2][4];
    #pragma unroll
    for (int i = 0; i < 2; i++)
        #pragma unroll
        for (int j = 0; j < 2; j++)
            #pragma unroll
            for (int t = 0; t < 4; t++) acc[i][j][t] = 0.f;

    const int arow_l = (lane & 7) + ((lane >> 3) & 1) * 8;
    const int akb_l  = (lane >> 4) * 16;
    const int brow_l = (lane & 7) + ((lane >> 4) & 1) * 8;
    const int bkb_l  = ((lane >> 3) & 1) * 16;

    const int ldrow = tid >> 3;
    const int ldq   = tid & 7;
    const uint32_t ldoff = (uint32_t)(ldq * 16);

    size_t srcA[2], srcB[2];
    uint32_t dsto[2];
    #pragma unroll
    for (int p = 0; p < 2; p++) {
        int row = p * 32 + ldrow;
        dsto[p] = (uint32_t)(row * 128) + (ldoff ^ (uint32_t)((row & 7) << 4));
        int lr = mbase + row;
        int ar = (MODE == 0) ? lr : ((lr >> 4) * KSEL + (lr & 15));
        srcA[p] = (size_t)ar * EDIM + ldq * 8;
        srcB[p] = (size_t)(nbase + row) * EDIM + ldq * 8;
    }

    #pragma unroll
    for (int p = 0; p < 2; p++) {
        CP_ASYNC16(smb + QA_HI + dsto[p], Ahi + srcA[p]);
        CP_ASYNC16(smb + QA_LO + dsto[p], Alo + srcA[p]);
        CP_ASYNC16(smb + QB_HI + dsto[p], Bhi + srcB[p]);
        CP_ASYNC16(smb + QB_LO + dsto[p], Blo + srcB[p]);
    }
    CP_COMMIT();

    #pragma unroll 1
    for (int c = 0; c < 8; c++) {
        if (c + 1 < 8) {
            const uint32_t sb = smb + ((c + 1) & 1) * QSTG;
            const size_t ko = (size_t)(c + 1) * 64;
            #pragma unroll
            for (int p = 0; p < 2; p++) {
                CP_ASYNC16(sb + QA_HI + dsto[p], Ahi + srcA[p] + ko);
                CP_ASYNC16(sb + QA_LO + dsto[p], Alo + srcA[p] + ko);
                CP_ASYNC16(sb + QB_HI + dsto[p], Bhi + srcB[p] + ko);
                CP_ASYNC16(sb + QB_LO + dsto[p], Blo + srcB[p] + ko);
            }
            CP_COMMIT();
            CP_WAIT(1);
        } else {
            CP_WAIT(0);
        }
        __syncthreads();

        const uint32_t sb = smb + (c & 1) * QSTG;
        #pragma unroll
        for (int kk = 0; kk < 4; kk++) {
            uint32_t ah[2][4], al[2][4];
            #pragma unroll
            for (int mt = 0; mt < 2; mt++) {
                int row = wm * 32 + mt * 16 + arow_l;
                uint32_t kb = (uint32_t)(kk * 32 + akb_l) ^ (uint32_t)((row & 7) << 4);
                uint32_t ad = (uint32_t)(row * 128) + kb;
                ldsm4(ah[mt], sb + QA_HI + ad);
                ldsm4(al[mt], sb + QA_LO + ad);
            }
            {
                int row = wn * 16 + brow_l;
                uint32_t kb = (uint32_t)(kk * 32 + bkb_l) ^ (uint32_t)((row & 7) << 4);
                uint32_t bd = (uint32_t)(row * 128) + kb;
                uint32_t bh[4], bl[4];
                ldsm4(bh, sb + QB_HI + bd);
                ldsm4(bl, sb + QB_LO + bd);
                mma_bf16(acc[0][0], ah[0], bh[0], bh[1]);
                mma_bf16(acc[1][0], ah[1], bh[0], bh[1]);
                mma_bf16(acc[0][1], ah[0], bh[2], bh[3]);
                mma_bf16(acc[1][1], ah[1], bh[2], bh[3]);
                mma_bf16(acc[0][0], ah[0], bl[0], bl[1]);
                mma_bf16(acc[1][0], ah[1], bl[0], bl[1]);
                mma_bf16(acc[0][1], ah[0], bl[2], bl[3]);
                mma_bf16(acc[1][1], ah[1], bl[2], bl[3]);
                mma_bf16(acc[0][0], al[0], bh[0], bh[1]);
                mma_bf16(acc[1][0], al[1], bh[0], bh[1]);
                mma_bf16(acc[0][1], al[0], bh[2], bh[3]);
                mma_bf16(acc[1][1], al[1], bh[2], bh[3]);
            }
        }
        __syncthreads();
    }

    const int rrow = lane >> 2;
    const int rcol = (lane & 3) * 2;
    #pragma unroll
    for (int mt = 0; mt < 2; mt++) {
        #pragma unroll
        for (int nt = 0; nt < 2; nt++) {
            int col = nbase + wn * 16 + nt * 8 + rcol;
            float b0 = bias[col], b1 = bias[col + 1];
            #pragma unroll
            for (int h = 0; h < 2; h++) {
                int r = mbase + wm * 32 + mt * 16 + rrow + h * 8;
                float v0 = acc[mt][nt][2*h]   + b0;
                float v1 = acc[mt][nt][2*h+1] + b1;
                size_t o = (size_t)r * EDIM + col;
                if (EPI == 0) {
                    *(float2*)&Cout[o] = make_float2(v0, v1);
                } else {
                    float g0 = 0.5f * v0 * (1.f + erff(v0 * 0.70710678118654752f));
                    float g1 = 0.5f * v1 * (1.f + erff(v1 * 0.70710678118654752f));
                    float2 yr = *(const float2*)&yres[o];
                    *(float2*)&Cout[o] = make_float2(yr.x + g0, yr.y + g1);
                }
            }
        }
    }
}

// ------------------------- attention (256 threads per (b,h)) ------------------
#define ATTN_SMEM ((16*64 + 16*512 + 128*65) * 4)

__global__ void __launch_bounds__(256)
attn_kernel(const float* __restrict__ qb, const float* __restrict__ kv,
            __nv_bfloat16* __restrict__ ohi, __nv_bfloat16* __restrict__ olo)
{
    extern __shared__ float smf[];
    float* s_q  = smf;
    float* s_l  = smf + 16 * 64;
    float* s_kv = smf + 16 * 64 + 16 * 512;
    const int b = blockIdx.x >> 3, h = blockIdx.x & 7;
    const int tid = threadIdx.x;            // 256

    const float* qbase = qb + ((size_t)b * TOUT) * EDIM + h * DH;
    for (int i = tid; i < 16 * 64; i += 256) {
        int t = i >> 6, d = i & 63;
        s_q[i] = qbase[(size_t)t * EDIM + d];
    }
    const float scale = 0.125f;

    for (int c = 0; c < 4; c++) {
        const float* kbase = kv + ((size_t)(b * KSEL + c * 128)) * 1024 + h * DH;
        __syncthreads();
        for (int i = tid; i < 128 * 64; i += 256) {
            int j = i >> 6, d = i & 63;
            s_kv[j * 65 + d] = kbase[(size_t)j * 1024 + d];
        }
        __syncthreads();
        {
            int j = tid & 127, half = tid >> 7;
            float acc[8];
            #pragma unroll
            for (int t = 0; t < 8; t++) acc[t] = 0.f;
            for (int d = 0; d < 64; d++) {
                float kd = s_kv[j * 65 + d];
                #pragma unroll
                for (int t = 0; t < 8; t++) acc[t] += s_q[(half * 8 + t) * 64 + d] * kd;
            }
            #pragma unroll
            for (int t = 0; t < 8; t++)
                s_l[(half * 8 + t) * 512 + c * 128 + j] = acc[t] * scale;
        }
    }
    __syncthreads();

    {
        int row = tid >> 4, l = tid & 15;
        float* lr = s_l + row * 512;
        float m = -1e30f;
        for (int j = l; j < 512; j += 16) m = fmaxf(m, lr[j]);
        for (int o = 8; o >= 1; o >>= 1) m = fmaxf(m, __shfl_xor_sync(0xffffffffu, m, o));
        float sum = 0.f;
        for (int j = l; j < 512; j += 16) { float e = expf(lr[j] - m); lr[j] = e; sum += e; }
        for (int o = 8; o >= 1; o >>= 1) sum += __shfl_xor_sync(0xffffffffu, sum, o);
        float inv = 1.f / sum;
        for (int j = l; j < 512; j += 16) lr[j] *= inv;
    }

    {
        int d = tid & 63, tg = tid >> 6;
        float acc[4];
        #pragma unroll
        for (int t = 0; t < 4; t++) acc[t] = 0.f;
        for (int c = 0; c < 4; c++) {
            const float* vbase = kv + ((size_t)(b * KSEL + c * 128)) * 1024 + 512 + h * DH;
            __syncthreads();
            for (int i = tid; i < 128 * 64; i += 256) {
                int j = i >> 6, dd = i & 63;
                s_kv[j * 65 + dd] = vbase[(size_t)j * 1024 + dd];
            }
            __syncthreads();
            for (int j = 0; j < 128; j++) {
                float vv = s_kv[j * 65 + d];
                #pragma unroll
                for (int t = 0; t < 4; t++)
                    acc[t] += s_l[(tg * 4 + t) * 512 + c * 128 + j] * vv;
            }
        }
        const size_t obase = ((size_t)b * TOUT) * EDIM + h * DH + d;
        #pragma unroll
        for (int t = 0; t < 4; t++) {
            __nv_bfloat16 hh, ll;
            split_bf16(acc[t], hh, ll);
            ohi[obase + (size_t)(tg * 4 + t) * EDIM] = hh;
            olo[obase + (size_t)(tg * 4 + t) * EDIM] = ll;
        }
    }
}

// ------------------------- residual + layernorm ------------------------------
__global__ void ln_kernel(const float* __restrict__ xq, const float* __restrict__ o2,
                          const float* __restrict__ g, const float* __restrict__ be,
                          float* __restrict__ y,
                          __nv_bfloat16* __restrict__ yhi, __nv_bfloat16* __restrict__ ylo)
{
    const int r = blockIdx.x;
    const float* xr = xq + (size_t)r * EDIM;
    const float* orow = o2 + (size_t)r * EDIM;
    const int tid = threadIdx.x;
    float v0 = xr[tid] + orow[tid];
    float v1 = xr[tid + 256] + orow[tid + 256];
    float s = v0 + v1, sq = v0 * v0 + v1 * v1;
    for (int o = 16; o >= 1; o >>= 1) {
        s  += __shfl_xor_sync(0xffffffffu, s, o);
        sq += __shfl_xor_sync(0xffffffffu, sq, o);
    }
    __shared__ float ss[8], ssq[8];
    __shared__ float mu, rstd;
    int w = tid >> 5;
    if ((tid & 31) == 0) { ss[w] = s; ssq[w] = sq; }
    __syncthreads();
    if (tid == 0) {
        float S = 0.f, SQ = 0.f;
        for (int i = 0; i < 8; i++) { S += ss[i]; SQ += ssq[i]; }
        float m = S / 512.f;
        float var = SQ / 512.f - m * m;
        mu = m; rstd = rsqrtf(var + 1e-5f);
    }
    __syncthreads();
    float y0 = (v0 - mu) * rstd * g[tid]       + be[tid];
    float y1 = (v1 - mu) * rstd * g[tid + 256] + be[tid + 256];
    y[(size_t)r * EDIM + tid]       = y0;
    y[(size_t)r * EDIM + tid + 256] = y1;
    __nv_bfloat16 h0, l0, h1, l1;
    split_bf16(y0, h0, l0); split_bf16(y1, h1, l1);
    yhi[(size_t)r * EDIM + tid]       = h0;
    ylo[(size_t)r * EDIM + tid]       = l0;
    yhi[(size_t)r * EDIM + tid + 256] = h1;
    ylo[(size_t)r * EDIM + tid + 256] = l1;
}

// ------------------------- launcher ------------------------------------------
extern "C" void kernel_launch(void* const* d_in, const int* in_sizes, int n_in,
                              void* d_out, int out_size)
{
    const float* ppf = (const float*)d_in[0];
    const float* sc  = (const float*)d_in[1];
    const float* pw  = (const float*)d_in[2];
    const float* pb  = (const float*)d_in[3];
    const float* ipw = (const float*)d_in[4];
    const float* ipb = (const float*)d_in[5];
    const float* opw = (const float*)d_in[6];
    const float* opb = (const float*)d_in[7];
    const float* lng = (const float*)d_in[8];
    const float* lnb = (const float*)d_in[9];
    const float* fw  = (const float*)d_in[10];
    const float* fb  = (const float*)d_in[11];
    float* out = (float*)d_out;

    int* idx;
    __nv_bfloat16 *wphi, *wplo, *wqhi, *wqlo, *wkvhi, *wkvlo;
    __nv_bfloat16 *wohi, *wolo, *wfhi, *wflo, *xhi, *xlo, *ohi, *olo, *yhi, *ylo;
    float *kv, *xq, *q, *o2, *y;
    cudaGetSymbolAddress((void**)&idx,   g_idx);
    cudaGetSymbolAddress((void**)&wphi,  g_wphi);
    cudaGetSymbolAddress((void**)&wplo,  g_wplo);
    cudaGetSymbolAddress((void**)&wqhi,  g_wqhi);
    cudaGetSymbolAddress((void**)&wqlo,  g_wqlo);
    cudaGetSymbolAddress((void**)&wkvhi, g_wkvhi);
    cudaGetSymbolAddress((void**)&wkvlo, g_wkvlo);
    cudaGetSymbolAddress((void**)&wohi,  g_wohi);
    cudaGetSymbolAddress((void**)&wolo,  g_wolo);
    cudaGetSymbolAddress((void**)&wfhi,  g_wfhi);
    cudaGetSymbolAddress((void**)&wflo,  g_wflo);
    cudaGetSymbolAddress((void**)&xhi,   g_xhi);
    cudaGetSymbolAddress((void**)&xlo,   g_xlo);
    cudaGetSymbolAddress((void**)&kv,    g_kv);
    cudaGetSymbolAddress((void**)&xq,    g_xq);
    cudaGetSymbolAddress((void**)&q,     g_q);
    cudaGetSymbolAddress((void**)&ohi,   g_ohi);
    cudaGetSymbolAddress((void**)&olo,   g_olo);
    cudaGetSymbolAddress((void**)&o2,    g_o2);
    cudaGetSymbolAddress((void**)&y,     g_y);
    cudaGetSymbolAddress((void**)&yhi,   g_yhi);
    cudaGetSymbolAddress((void**)&ylo,   g_ylo);

    cudaFuncSetAttribute(gather_gemm,     cudaFuncAttributeMaxDynamicSharedMemorySize, GTH_SMEM);
    cudaFuncSetAttribute(kv_gemm,         cudaFuncAttributeMaxDynamicSharedMemorySize, KV_SMEM);
    cudaFuncSetAttribute(small_gemm<0,1>, cudaFuncAttributeMaxDynamicSharedMemorySize, SGEMM_SMEM);
    cudaFuncSetAttribute(small_gemm<0,0>, cudaFuncAttributeMaxDynamicSharedMemorySize, SGEMM_SMEM);
    cudaFuncSetAttribute(small_gemm<2,0>, cudaFuncAttributeMaxDynamicSharedMemorySize, SGEMM_SMEM);
    cudaFuncSetAttribute(attn_kernel,     cudaFuncAttributeMaxDynamicSharedMemorySize, ATTN_SMEM);

    // 1) topk (hist also converts weights + zeroes g_cnt)
    topk_hist<<<128, 256>>>(sc, pw, ipw, opw, fw);
    topk_filter<<<128, 256>>>(sc);
    topk_final<<<16, 512>>>(idx);

    // 2) x = gather(ppf) @ proj_w^T + pb  (R12-proven 128x128 fused kernel)
    gather_gemm<<<dim3(64, 4), 256, GTH_SMEM>>>(wphi, wplo, pb, xq, xhi, xlo, ppf, idx);

    // 3) kv = x @ Wkv^T + b  (128x64 tiles, 512 thr, 2 CTAs/SM = 32 warps/SM)
    kv_gemm<<<dim3(64, 16), 512, KV_SMEM>>>(xhi, xlo, wkvhi, wkvlo, ipb + EDIM, kv);

    // 4) q = x[:, :16] @ Wq^T + b
    small_gemm<0,1><<<dim3(4, 8), 256, SGEMM_SMEM>>>(xhi, xlo, wqhi, wqlo, ipb, nullptr, q);

    // 5) attention -> o (bf16 hi/lo)
    attn_kernel<<<128, 256, ATTN_SMEM>>>(q, kv, ohi, olo);

    // 6) out_proj
    small_gemm<0,0><<<dim3(4, 8), 256, SGEMM_SMEM>>>(ohi, olo, wohi, wolo, opb, nullptr, o2);

    // 7) residual + layernorm
    ln_kernel<<<256, 256>>>(xq, o2, lng, lnb, y, yhi, ylo);

    // 8) FFN GEMM + fused gelu + residual -> out
    small_gemm<2,0><<<dim3(4, 8), 256, SGEMM_SMEM>>>(yhi, ylo, wfhi, wflo, fb, y, out);
}

// round 17
// speedup vs baseline: 1.0850x; 1.0819x over previous
#include <cuda_runtime.h>
#include <cuda_bf16.h>
#include <cstdint>

#define B_SZ   16
#define NPTS   32768
#define DFEAT  256
#define EDIM   512
#define KSEL   512
#define HEADS  8
#define DH     64
#define TOUT   16
#define CAND_MAX 4096

// ------------------------- scratch (device globals, no allocs) ----------------
__device__ int   g_idx[B_SZ * KSEL];
__device__ unsigned int g_hist[B_SZ * 8 * 256];
__device__ int   g_cnt[B_SZ];
__device__ unsigned long long g_cand[B_SZ * CAND_MAX];
__device__ __nv_bfloat16 g_wphi[EDIM * DFEAT];
__device__ __nv_bfloat16 g_wplo[EDIM * DFEAT];
__device__ __nv_bfloat16 g_wqhi[EDIM * EDIM];
__device__ __nv_bfloat16 g_wqlo[EDIM * EDIM];
__device__ __nv_bfloat16 g_wkvhi[2 * EDIM * EDIM];
__device__ __nv_bfloat16 g_wkvlo[2 * EDIM * EDIM];
__device__ __nv_bfloat16 g_wohi[EDIM * EDIM];
__device__ __nv_bfloat16 g_wolo[EDIM * EDIM];
__device__ __nv_bfloat16 g_wfhi[EDIM * EDIM];
__device__ __nv_bfloat16 g_wflo[EDIM * EDIM];
__device__ __nv_bfloat16 g_xhi[B_SZ * KSEL * EDIM];
__device__ __nv_bfloat16 g_xlo[B_SZ * KSEL * EDIM];
__device__ float g_kv[B_SZ * KSEL * 2 * EDIM];   // row stride 1024: [k | v]
__device__ float g_xq[B_SZ * TOUT * EDIM];
__device__ float g_q [B_SZ * TOUT * EDIM];
__device__ __nv_bfloat16 g_ohi[B_SZ * TOUT * EDIM];
__device__ __nv_bfloat16 g_olo[B_SZ * TOUT * EDIM];
__device__ float g_o2[B_SZ * TOUT * EDIM];
__device__ float g_y [B_SZ * TOUT * EDIM];
__device__ __nv_bfloat16 g_yhi[B_SZ * TOUT * EDIM];
__device__ __nv_bfloat16 g_ylo[B_SZ * TOUT * EDIM];

// ------------------------- helpers -------------------------------------------
__device__ __forceinline__ uint32_t smem_u32(const void* p) {
    uint32_t a;
    asm("{ .reg .u64 t; cvta.to.shared.u64 t, %1; cvt.u32.u64 %0, t; }" : "=r"(a) : "l"(p));
    return a;
}
__device__ __forceinline__ void ldsm4(uint32_t (&r)[4], uint32_t addr) {
    asm volatile("ldmatrix.sync.aligned.m8n8.x4.shared.b16 {%0,%1,%2,%3}, [%4];"
                 : "=r"(r[0]), "=r"(r[1]), "=r"(r[2]), "=r"(r[3]) : "r"(addr));
}
__device__ __forceinline__ void mma_bf16(float (&d)[4], const uint32_t (&a)[4],
                                         uint32_t b0, uint32_t b1) {
    asm volatile("mma.sync.aligned.m16n8k16.row.col.f32.bf16.bf16.f32 "
                 "{%0,%1,%2,%3}, {%4,%5,%6,%7}, {%8,%9}, {%0,%1,%2,%3};"
                 : "+f"(d[0]), "+f"(d[1]), "+f"(d[2]), "+f"(d[3])
                 : "r"(a[0]), "r"(a[1]), "r"(a[2]), "r"(a[3]), "r"(b0), "r"(b1));
}
#define CP_ASYNC16(dst, src) \
    asm volatile("cp.async.cg.shared.global [%0], [%1], 16;" :: "r"(dst), "l"(src))
#define CP_COMMIT() asm volatile("cp.async.commit_group;")
#define CP_WAIT(n)  asm volatile("cp.async.wait_group %0;" :: "n"(n))

__device__ __forceinline__ unsigned int f2u(float f) {
    unsigned int u = __float_as_uint(f);
    return (u & 0x80000000u) ? ~u : (u | 0x80000000u);
}
__device__ __forceinline__ void split_bf16(float f, __nv_bfloat16& h, __nv_bfloat16& l) {
    h = __float2bfloat16_rn(f);
    l = __float2bfloat16_rn(f - __bfloat162float(h));
}

// weight layout (element counts)
#define NW_P  (EDIM * DFEAT)
#define NW_Q  (EDIM * EDIM)
#define NW_KV (2 * EDIM * EDIM)
#define NW_O  (EDIM * EDIM)
#define NW_TOTAL (NW_P + NW_Q + NW_KV + NW_O + NW_O)

__device__ __forceinline__ void convert_one_weight(int i, const float* pw, const float* ipw,
                                                   const float* opw, const float* fw) {
    __nv_bfloat16 h, l;
    if (i < NW_P) {
        split_bf16(pw[i], h, l);
        g_wphi[i] = h; g_wplo[i] = l;
    } else if (i < NW_P + NW_Q) {
        int j = i - NW_P;
        split_bf16(ipw[j], h, l);
        g_wqhi[j] = h; g_wqlo[j] = l;
    } else if (i < NW_P + NW_Q + NW_KV) {
        int j = i - NW_P - NW_Q;
        split_bf16(ipw[NW_Q + j], h, l);
        g_wkvhi[j] = h; g_wkvlo[j] = l;
    } else if (i < NW_P + NW_Q + NW_KV + NW_O) {
        int j = i - NW_P - NW_Q - NW_KV;
        split_bf16(opw[j], h, l);
        g_wohi[j] = h; g_wolo[j] = l;
    } else {
        int j = i - NW_P - NW_Q - NW_KV - NW_O;
        split_bf16(fw[j], h, l);
        g_wfhi[j] = h; g_wflo[j] = l;
    }
}

// ------------------------- topk T1: per-slice hist + weight convert ----------
__global__ void topk_hist(const float* __restrict__ scores,
                          const float* __restrict__ pw, const float* __restrict__ ipw,
                          const float* __restrict__ opw, const float* __restrict__ fw) {
    const int b = blockIdx.x >> 3, s = blockIdx.x & 7;
    const float* sp = scores + (size_t)b * NPTS + s * 4096;
    __shared__ unsigned int h[256];
    const int tid = threadIdx.x;
    h[tid] = 0;
    if (tid == 0 && s == 0) g_cnt[b] = 0;
    __syncthreads();
    #pragma unroll
    for (int j = 0; j < 16; j++) {
        unsigned int u = f2u(sp[tid + j * 256]);
        atomicAdd(&h[u >> 24], 1u);
    }
    __syncthreads();
    g_hist[(b * 8 + s) * 256 + tid] = h[tid];
    for (int i = blockIdx.x * 256 + tid; i < NW_TOTAL; i += 128 * 256)
        convert_one_weight(i, pw, ipw, opw, fw);
}

// T2: byte threshold per batch, compact candidates
__global__ void topk_filter(const float* __restrict__ scores) {
    const int b = blockIdx.x >> 3, s = blockIdx.x & 7;
    const int tid = threadIdx.x;
    __shared__ unsigned int h[256];
    __shared__ int sh_b0;
    unsigned int acc8 = 0;
    #pragma unroll
    for (int ss = 0; ss < 8; ss++) acc8 += g_hist[(b * 8 + ss) * 256 + tid];
    h[tid] = acc8;
    __syncthreads();
    if (tid == 0) {
        int acc = 0, byte = 255;
        for (; byte >= 0; byte--) { acc += (int)h[byte]; if (acc >= KSEL) break; }
        sh_b0 = byte;
    }
    __syncthreads();
    const unsigned int thr = (unsigned int)sh_b0 << 24;
    const float* sp = scores + (size_t)b * NPTS + s * 4096;
    #pragma unroll
    for (int j = 0; j < 16; j++) {
        int i = tid + j * 256;
        unsigned int u = f2u(sp[i]);
        if (u >= thr) {
            int p = atomicAdd(&g_cnt[b], 1);
            if (p < CAND_MAX) {
                unsigned int gi = (unsigned int)(s * 4096 + i);
                g_cand[b * CAND_MAX + p] = ((unsigned long long)u << 32) | (unsigned int)(~gi);
            }
        }
    }
}

// T3: sort candidates desc by (value, ~idx)
__global__ void topk_final(int* __restrict__ out_idx) {
    const int b = blockIdx.x;
    const int tid = threadIdx.x;   // 512
    __shared__ unsigned long long sk[CAND_MAX];
    int n = g_cnt[b];
    if (n > CAND_MAX) n = CAND_MAX;
    int n2 = 512;
    while (n2 < n) n2 <<= 1;
    for (int i = tid; i < n2; i += 512)
        sk[i] = (i < n) ? g_cand[b * CAND_MAX + i] : 0ull;
    __syncthreads();
    for (int size = 2; size <= n2; size <<= 1)
        for (int stride = size >> 1; stride >= 1; stride >>= 1) {
            for (int t = tid; t < (n2 >> 1); t += 512) {
                int low = t & (stride - 1);
                int i = ((t - low) << 1) | low;
                int j = i | stride;
                unsigned long long a = sk[i], c = sk[j];
                bool desc = ((i & size) == 0);
                if (desc ? (a < c) : (a > c)) { sk[i] = c; sk[j] = a; }
            }
            __syncthreads();
        }
    if (tid < KSEL)
        out_idx[b * KSEL + tid] = (int)(~(unsigned int)(sk[tid] & 0xFFFFFFFFu));
}

// ------------------------- gather split-bf16 GEMM (CTA 128x128, 256 thr) -----
// R12-proven: fp32 staging in SMEM, 2 CTAs/SM.
#define GTH_SMEM 98304

__global__ void __launch_bounds__(256, 2)
gather_gemm(const __nv_bfloat16* __restrict__ Bhi, const __nv_bfloat16* __restrict__ Blo,
            const float* __restrict__ bias,
            float* __restrict__ Cfp, __nv_bfloat16* __restrict__ Chi, __nv_bfloat16* __restrict__ Clo,
            const float* __restrict__ Afp, const int* __restrict__ idxp)
{
    extern __shared__ char sm[];
    const uint32_t smb = smem_u32(sm);
    const uint32_t AF32 = 0;
    const uint32_t AHI = 32768u;
    const uint32_t ALO = AHI + 16384u;
    const uint32_t BHI = ALO + 16384u;
    const uint32_t BLO = BHI + 16384u;
    const int K = DFEAT;

    const int tid  = threadIdx.x;
    const int wid  = tid >> 5;
    const int lane = tid & 31;
    const int wm = wid & 3;
    const int wn = wid >> 2;
    const int mbase = blockIdx.x * 128;
    const int nbase = blockIdx.y * 128;

    float acc[2][8][4];
    #pragma unroll
    for (int i = 0; i < 2; i++)
        #pragma unroll
        for (int j = 0; j < 8; j++)
            #pragma unroll
            for (int t = 0; t < 4; t++) acc[i][j][t] = 0.f;

    const int arow_l = (lane & 7) + ((lane >> 3) & 1) * 8;
    const int akb_l  = (lane >> 4) * 16;
    const int brow_l = (lane & 7) + ((lane >> 4) & 1) * 8;
    const int bkb_l  = ((lane >> 3) & 1) * 16;

    const int ldrow = tid >> 3;
    const int ldq   = tid & 7;
    const uint32_t ldoff = (uint32_t)(ldq * 16);

    const float* aptr[8];
    #pragma unroll
    for (int p = 0; p < 8; p++) {
        int row = p * 16 + (tid >> 4);
        int lr = mbase + row;
        int bb = lr >> 9;
        aptr[p] = Afp + ((size_t)bb * NPTS + (size_t)idxp[lr]) * DFEAT + (tid & 15) * 4;
    }

    for (int c = 0; c < 4; c++) {
        __syncthreads();
        {
            const uint32_t aq16 = (uint32_t)((tid & 15) * 16);
            #pragma unroll
            for (int p = 0; p < 8; p++) {
                int row = p * 16 + (tid >> 4);
                CP_ASYNC16(smb + AF32 + (uint32_t)(row * 256) + aq16, aptr[p] + c * 64);
            }
        }
        #pragma unroll
        for (int p = 0; p < 4; p++) {
            int row = p * 32 + ldrow;
            uint32_t dsto = (uint32_t)(row * 128) + (ldoff ^ (uint32_t)((row & 7) << 4));
            size_t srcb = (size_t)(nbase + row) * K + c * 64 + ldq * 8;
            CP_ASYNC16(smb + BHI + dsto, Bhi + srcb);
            CP_ASYNC16(smb + BLO + dsto, Blo + srcb);
        }
        CP_COMMIT();
        CP_WAIT(0);
        __syncthreads();

        #pragma unroll
        for (int it = 0; it < 8; it++) {
            int f4 = tid + it * 256;
            int row = f4 >> 4, c4 = f4 & 15;
            float4 v = *(const float4*)(sm + AF32 + (size_t)f4 * 16);
            __nv_bfloat16 h0,h1,h2,h3,l0,l1,l2,l3;
            split_bf16(v.x,h0,l0); split_bf16(v.y,h1,l1);
            split_bf16(v.z,h2,l2); split_bf16(v.w,h3,l3);
            uint32_t off = (uint32_t)(row * 128) + (uint32_t)((c4 * 8) ^ ((row & 7) << 4));
            *(__nv_bfloat162*)(sm + AHI + off)     = __nv_bfloat162{h0, h1};
            *(__nv_bfloat162*)(sm + AHI + off + 4) = __nv_bfloat162{h2, h3};
            *(__nv_bfloat162*)(sm + ALO + off)     = __nv_bfloat162{l0, l1};
            *(__nv_bfloat162*)(sm + ALO + off + 4) = __nv_bfloat162{l2, l3};
        }
        __syncthreads();

        #pragma unroll
        for (int kk = 0; kk < 4; kk++) {
            uint32_t ah[2][4], al[2][4];
            #pragma unroll
            for (int mt = 0; mt < 2; mt++) {
                int row = wm * 32 + mt * 16 + arow_l;
                uint32_t kb = (uint32_t)(kk * 32 + akb_l) ^ (uint32_t)((row & 7) << 4);
                uint32_t ad = (uint32_t)(row * 128) + kb;
                ldsm4(ah[mt], smb + AHI + ad);
                ldsm4(al[mt], smb + ALO + ad);
            }
            #pragma unroll
            for (int np = 0; np < 4; np++) {
                int row = wn * 64 + np * 16 + brow_l;
                uint32_t kb = (uint32_t)(kk * 32 + bkb_l) ^ (uint32_t)((row & 7) << 4);
                uint32_t bd = (uint32_t)(row * 128) + kb;
                uint32_t bh[4], bl[4];
                ldsm4(bh, smb + BHI + bd);
                ldsm4(bl, smb + BLO + bd);
                mma_bf16(acc[0][2*np],   ah[0], bh[0], bh[1]);
                mma_bf16(acc[1][2*np],   ah[1], bh[0], bh[1]);
                mma_bf16(acc[0][2*np+1], ah[0], bh[2], bh[3]);
                mma_bf16(acc[1][2*np+1], ah[1], bh[2], bh[3]);
                mma_bf16(acc[0][2*np],   ah[0], bl[0], bl[1]);
                mma_bf16(acc[1][2*np],   ah[1], bl[0], bl[1]);
                mma_bf16(acc[0][2*np+1], ah[0], bl[2], bl[3]);
                mma_bf16(acc[1][2*np+1], ah[1], bl[2], bl[3]);
                mma_bf16(acc[0][2*np],   al[0], bh[0], bh[1]);
                mma_bf16(acc[1][2*np],   al[1], bh[0], bh[1]);
                mma_bf16(acc[0][2*np+1], al[0], bh[2], bh[3]);
                mma_bf16(acc[1][2*np+1], al[1], bh[2], bh[3]);
            }
        }
    }

    const int rrow = lane >> 2;
    const int rcol = (lane & 3) * 2;
    #pragma unroll
    for (int mt = 0; mt < 2; mt++) {
        #pragma unroll
        for (int nt = 0; nt < 8; nt++) {
            int col = nbase + wn * 64 + nt * 8 + rcol;
            float b0 = bias[col], b1 = bias[col + 1];
            #pragma unroll
            for (int h = 0; h < 2; h++) {
                int r = mbase + wm * 32 + mt * 16 + rrow + h * 8;
                float v0 = acc[mt][nt][2*h]   + b0;
                float v1 = acc[mt][nt][2*h+1] + b1;
                __nv_bfloat16 h0, h1, l0, l1;
                split_bf16(v0, h0, l0); split_bf16(v1, h1, l1);
                size_t o = (size_t)r * EDIM + col;
                *(__nv_bfloat162*)&Chi[o] = __nv_bfloat162{h0, h1};
                *(__nv_bfloat162*)&Clo[o] = __nv_bfloat162{l0, l1};
                int t = r & 511, bb = r >> 9;
                if (t < TOUT) {
                    size_t oq = (size_t)(bb * TOUT + t) * EDIM + col;
                    *(float2*)&Cfp[oq] = make_float2(v0, v1);
                }
            }
        }
    }
}

// ------------------------- KV GEMM: CTA 128x64, 3 CTAs/SM (R12, proven) ------
#define KVA_HI 0
#define KVA_LO 16384
#define KVB_HI 32768
#define KVB_LO 40960
#define KV_SMEM 49152

__global__ void __launch_bounds__(256, 3)
kv_gemm(const __nv_bfloat16* __restrict__ Ahi, const __nv_bfloat16* __restrict__ Alo,
        const __nv_bfloat16* __restrict__ Bhi, const __nv_bfloat16* __restrict__ Blo,
        const float* __restrict__ bias, float* __restrict__ C)
{
    extern __shared__ char sm[];
    const uint32_t smb = smem_u32(sm);
    const int tid  = threadIdx.x;
    const int wid  = tid >> 5;
    const int lane = tid & 31;
    const int wm = wid & 3;
    const int wn = wid >> 2;
    const int mbase = blockIdx.x * 128;
    const int nbase = blockIdx.y * 64;

    float acc[2][4][4];
    #pragma unroll
    for (int i = 0; i < 2; i++)
        #pragma unroll
        for (int j = 0; j < 4; j++)
            #pragma unroll
            for (int t = 0; t < 4; t++) acc[i][j][t] = 0.f;

    const int arow_l = (lane & 7) + ((lane >> 3) & 1) * 8;
    const int akb_l  = (lane >> 4) * 16;
    const int brow_l = (lane & 7) + ((lane >> 4) & 1) * 8;
    const int bkb_l  = ((lane >> 3) & 1) * 16;

    const int ldrow = tid >> 3;
    const int ldq   = tid & 7;
    const uint32_t ldoff = (uint32_t)(ldq * 16);

    for (int c = 0; c < 8; c++) {
        __syncthreads();
        #pragma unroll
        for (int p = 0; p < 4; p++) {
            int row = p * 32 + ldrow;
            uint32_t dsto = (uint32_t)(row * 128) + (ldoff ^ (uint32_t)((row & 7) << 4));
            size_t srca = (size_t)(mbase + row) * EDIM + c * 64 + ldq * 8;
            CP_ASYNC16(smb + KVA_HI + dsto, Ahi + srca);
            CP_ASYNC16(smb + KVA_LO + dsto, Alo + srca);
        }
        #pragma unroll
        for (int p = 0; p < 2; p++) {
            int row = p * 32 + ldrow;
            uint32_t dsto = (uint32_t)(row * 128) + (ldoff ^ (uint32_t)((row & 7) << 4));
            size_t srcb = (size_t)(nbase + row) * EDIM + c * 64 + ldq * 8;
            CP_ASYNC16(smb + KVB_HI + dsto, Bhi + srcb);
            CP_ASYNC16(smb + KVB_LO + dsto, Blo + srcb);
        }
        CP_COMMIT();
        CP_WAIT(0);
        __syncthreads();

        #pragma unroll
        for (int kk = 0; kk < 4; kk++) {
            uint32_t ah[2][4], al[2][4];
            #pragma unroll
            for (int mt = 0; mt < 2; mt++) {
                int row = wm * 32 + mt * 16 + arow_l;
                uint32_t kb = (uint32_t)(kk * 32 + akb_l) ^ (uint32_t)((row & 7) << 4);
                uint32_t ad = (uint32_t)(row * 128) + kb;
                ldsm4(ah[mt], smb + KVA_HI + ad);
                ldsm4(al[mt], smb + KVA_LO + ad);
            }
            #pragma unroll
            for (int np = 0; np < 2; np++) {
                int row = wn * 32 + np * 16 + brow_l;
                uint32_t kb = (uint32_t)(kk * 32 + bkb_l) ^ (uint32_t)((row & 7) << 4);
                uint32_t bd = (uint32_t)(row * 128) + kb;
                uint32_t bh[4], bl[4];
                ldsm4(bh, smb + KVB_HI + bd);
                ldsm4(bl, smb + KVB_LO + bd);
                mma_bf16(acc[0][2*np],   ah[0], bh[0], bh[1]);
                mma_bf16(acc[1][2*np],   ah[1], bh[0], bh[1]);
                mma_bf16(acc[0][2*np+1], ah[0], bh[2], bh[3]);
                mma_bf16(acc[1][2*np+1], ah[1], bh[2], bh[3]);
                mma_bf16(acc[0][2*np],   ah[0], bl[0], bl[1]);
                mma_bf16(acc[1][2*np],   ah[1], bl[0], bl[1]);
                mma_bf16(acc[0][2*np+1], ah[0], bl[2], bl[3]);
                mma_bf16(acc[1][2*np+1], ah[1], bl[2], bl[3]);
                mma_bf16(acc[0][2*np],   al[0], bh[0], bh[1]);
                mma_bf16(acc[1][2*np],   al[1], bh[0], bh[1]);
                mma_bf16(acc[0][2*np+1], al[0], bh[2], bh[3]);
                mma_bf16(acc[1][2*np+1], al[1], bh[2], bh[3]);
            }
        }
    }

    const int rrow = lane >> 2;
    const int rcol = (lane & 3) * 2;
    #pragma unroll
    for (int mt = 0; mt < 2; mt++) {
        #pragma unroll
        for (int nt = 0; nt < 4; nt++) {
            int col = nbase + wn * 32 + nt * 8 + rcol;
            float b0 = bias[col], b1 = bias[col + 1];
            #pragma unroll
            for (int h = 0; h < 2; h++) {
                int r = mbase + wm * 32 + mt * 16 + rrow + h * 8;
                float v0 = acc[mt][nt][2*h]   + b0;
                float v1 = acc[mt][nt][2*h+1] + b1;
                *(float2*)&C[(size_t)r * 1024 + col] = make_float2(v0, v1);
            }
        }
    }
}

// ------------------------- small-M split-bf16 GEMM (CTA 64x64, 2-stage) -------
#define QA_HI 0
#define QA_LO 8192
#define QB_HI 16384
#define QB_LO 24576
#define QSTG  32768
#define SGEMM_SMEM (2 * QSTG)

template<int EPI, int MODE>
__global__ void __launch_bounds__(256, 2)
small_gemm(const __nv_bfloat16* __restrict__ Ahi, const __nv_bfloat16* __restrict__ Alo,
           const __nv_bfloat16* __restrict__ Bhi, const __nv_bfloat16* __restrict__ Blo,
           const float* __restrict__ bias, const float* __restrict__ yres,
           float* __restrict__ Cout)
{
    extern __shared__ char sm[];
    const uint32_t smb = smem_u32(sm);
    const int tid  = threadIdx.x;
    const int wid  = tid >> 5;
    const int lane = tid & 31;
    const int wm = wid & 1;
    const int wn = wid >> 1;
    const int mbase = blockIdx.x * 64;
    const int nbase = blockIdx.y * 64;

    float acc[2][2][4];
    #pragma unroll
    for (int i = 0; i < 2; i++)
        #pragma unroll
        for (int j = 0; j < 2; j++)
            #pragma unroll
            for (int t = 0; t < 4; t++) acc[i][j][t] = 0.f;

    const int arow_l = (lane & 7) + ((lane >> 3) & 1) * 8;
    const int akb_l  = (lane >> 4) * 16;
    const int brow_l = (lane & 7) + ((lane >> 4) & 1) * 8;
    const int bkb_l  = ((lane >> 3) & 1) * 16;

    const int ldrow = tid >> 3;
    const int ldq   = tid & 7;
    const uint32_t ldoff = (uint32_t)(ldq * 16);

    size_t srcA[2], srcB[2];
    uint32_t dsto[2];
    #pragma unroll
    for (int p = 0; p < 2; p++) {
        int row = p * 32 + ldrow;
        dsto[p] = (uint32_t)(row * 128) + (ldoff ^ (uint32_t)((row & 7) << 4));
        int lr = mbase + row;
        int ar = (MODE == 0) ? lr : ((lr >> 4) * KSEL + (lr & 15));
        srcA[p] = (size_t)ar * EDIM + ldq * 8;
        srcB[p] = (size_t)(nbase + row) * EDIM + ldq * 8;
    }

    #pragma unroll
    for (int p = 0; p < 2; p++) {
        CP_ASYNC16(smb + QA_HI + dsto[p], Ahi + srcA[p]);
        CP_ASYNC16(smb + QA_LO + dsto[p], Alo + srcA[p]);
        CP_ASYNC16(smb + QB_HI + dsto[p], Bhi + srcB[p]);
        CP_ASYNC16(smb + QB_LO + dsto[p], Blo + srcB[p]);
    }
    CP_COMMIT();

    #pragma unroll 1
    for (int c = 0; c < 8; c++) {
        if (c + 1 < 8) {
            const uint32_t sb = smb + ((c + 1) & 1) * QSTG;
            const size_t ko = (size_t)(c + 1) * 64;
            #pragma unroll
            for (int p = 0; p < 2; p++) {
                CP_ASYNC16(sb + QA_HI + dsto[p], Ahi + srcA[p] + ko);
                CP_ASYNC16(sb + QA_LO + dsto[p], Alo + srcA[p] + ko);
                CP_ASYNC16(sb + QB_HI + dsto[p], Bhi + srcB[p] + ko);
                CP_ASYNC16(sb + QB_LO + dsto[p], Blo + srcB[p] + ko);
            }
            CP_COMMIT();
            CP_WAIT(1);
        } else {
            CP_WAIT(0);
        }
        __syncthreads();

        const uint32_t sb = smb + (c & 1) * QSTG;
        #pragma unroll
        for (int kk = 0; kk < 4; kk++) {
            uint32_t ah[2][4], al[2][4];
            #pragma unroll
            for (int mt = 0; mt < 2; mt++) {
                int row = wm * 32 + mt * 16 + arow_l;
                uint32_t kb = (uint32_t)(kk * 32 + akb_l) ^ (uint32_t)((row & 7) << 4);
                uint32_t ad = (uint32_t)(row * 128) + kb;
                ldsm4(ah[mt], sb + QA_HI + ad);
                ldsm4(al[mt], sb + QA_LO + ad);
            }
            {
                int row = wn * 16 + brow_l;
                uint32_t kb = (uint32_t)(kk * 32 + bkb_l) ^ (uint32_t)((row & 7) << 4);
                uint32_t bd = (uint32_t)(row * 128) + kb;
                uint32_t bh[4], bl[4];
                ldsm4(bh, sb + QB_HI + bd);
                ldsm4(bl, sb + QB_LO + bd);
                mma_bf16(acc[0][0], ah[0], bh[0], bh[1]);
                mma_bf16(acc[1][0], ah[1], bh[0], bh[1]);
                mma_bf16(acc[0][1], ah[0], bh[2], bh[3]);
                mma_bf16(acc[1][1], ah[1], bh[2], bh[3]);
                mma_bf16(acc[0][0], ah[0], bl[0], bl[1]);
                mma_bf16(acc[1][0], ah[1], bl[0], bl[1]);
                mma_bf16(acc[0][1], ah[0], bl[2], bl[3]);
                mma_bf16(acc[1][1], ah[1], bl[2], bl[3]);
                mma_bf16(acc[0][0], al[0], bh[0], bh[1]);
                mma_bf16(acc[1][0], al[1], bh[0], bh[1]);
                mma_bf16(acc[0][1], al[0], bh[2], bh[3]);
                mma_bf16(acc[1][1], al[1], bh[2], bh[3]);
            }
        }
        __syncthreads();
    }

    const int rrow = lane >> 2;
    const int rcol = (lane & 3) * 2;
    #pragma unroll
    for (int mt = 0; mt < 2; mt++) {
        #pragma unroll
        for (int nt = 0; nt < 2; nt++) {
            int col = nbase + wn * 16 + nt * 8 + rcol;
            float b0 = bias[col], b1 = bias[col + 1];
            #pragma unroll
            for (int h = 0; h < 2; h++) {
                int r = mbase + wm * 32 + mt * 16 + rrow + h * 8;
                float v0 = acc[mt][nt][2*h]   + b0;
                float v1 = acc[mt][nt][2*h+1] + b1;
                size_t o = (size_t)r * EDIM + col;
                if (EPI == 0) {
                    *(float2*)&Cout[o] = make_float2(v0, v1);
                } else {
                    float g0 = 0.5f * v0 * (1.f + erff(v0 * 0.70710678118654752f));
                    float g1 = 0.5f * v1 * (1.f + erff(v1 * 0.70710678118654752f));
                    float2 yr = *(const float2*)&yres[o];
                    *(float2*)&Cout[o] = make_float2(yr.x + g0, yr.y + g1);
                }
            }
        }
    }
}

// ------------------------- attention (512 threads per (b,h)) ------------------
#define ATTN_SMEM ((16*64 + 16*512 + 128*65) * 4)

__global__ void __launch_bounds__(512)
attn_kernel(const float* __restrict__ qb, const float* __restrict__ kv,
            __nv_bfloat16* __restrict__ ohi, __nv_bfloat16* __restrict__ olo)
{
    extern __shared__ float smf[];
    float* s_q  = smf;
    float* s_l  = smf + 16 * 64;
    float* s_kv = smf + 16 * 64 + 16 * 512;
    const int b = blockIdx.x >> 3, h = blockIdx.x & 7;
    const int tid = threadIdx.x;            // 512

    const float* qbase = qb + ((size_t)b * TOUT) * EDIM + h * DH;
    for (int i = tid; i < 16 * 64; i += 512) {
        int t = i >> 6, d = i & 63;
        s_q[i] = qbase[(size_t)t * EDIM + d];
    }
    const float scale = 0.125f;

    // QK: thread (j = tid&127, qg = tid>>7) -> 4 queries each (qg*4 .. qg*4+3)
    for (int c = 0; c < 4; c++) {
        const float* kbase = kv + ((size_t)(b * KSEL + c * 128)) * 1024 + h * DH;
        __syncthreads();
        for (int i = tid; i < 128 * 64; i += 512) {
            int j = i >> 6, d = i & 63;
            s_kv[j * 65 + d] = kbase[(size_t)j * 1024 + d];
        }
        __syncthreads();
        {
            int j = tid & 127, qg = tid >> 7;   // qg in 0..3
            float acc[4];
            #pragma unroll
            for (int t = 0; t < 4; t++) acc[t] = 0.f;
            for (int d = 0; d < 64; d++) {
                float kd = s_kv[j * 65 + d];
                #pragma unroll
                for (int t = 0; t < 4; t++) acc[t] += s_q[(qg * 4 + t) * 64 + d] * kd;
            }
            #pragma unroll
            for (int t = 0; t < 4; t++)
                s_l[(qg * 4 + t) * 512 + c * 128 + j] = acc[t] * scale;
        }
    }
    __syncthreads();

    // softmax: full warp (32 lanes) per row, 16 rows
    {
        int row = tid >> 5, l = tid & 31;
        float* lr = s_l + row * 512;
        float m = -1e30f;
        for (int j = l; j < 512; j += 32) m = fmaxf(m, lr[j]);
        for (int o = 16; o >= 1; o >>= 1) m = fmaxf(m, __shfl_xor_sync(0xffffffffu, m, o));
        float sum = 0.f;
        for (int j = l; j < 512; j += 32) { float e = expf(lr[j] - m); lr[j] = e; sum += e; }
        for (int o = 16; o >= 1; o >>= 1) sum += __shfl_xor_sync(0xffffffffu, sum, o);
        float inv = 1.f / sum;
        for (int j = l; j < 512; j += 32) lr[j] *= inv;
    }

    // PV: thread (d = tid&63, tg = tid>>6 in 0..7) -> 2 queries each
    {
        int d = tid & 63, tg = tid >> 6;
        float acc[2];
        acc[0] = 0.f; acc[1] = 0.f;
        for (int c = 0; c < 4; c++) {
            const float* vbase = kv + ((size_t)(b * KSEL + c * 128)) * 1024 + 512 + h * DH;
            __syncthreads();
            for (int i = tid; i < 128 * 64; i += 512) {
                int j = i >> 6, dd = i & 63;
                s_kv[j * 65 + dd] = vbase[(size_t)j * 1024 + dd];
            }
            __syncthreads();
            for (int j = 0; j < 128; j++) {
                float vv = s_kv[j * 65 + d];
                acc[0] += s_l[(tg * 2 + 0) * 512 + c * 128 + j] * vv;
                acc[1] += s_l[(tg * 2 + 1) * 512 + c * 128 + j] * vv;
            }
        }
        const size_t obase = ((size_t)b * TOUT) * EDIM + h * DH + d;
        #pragma unroll
        for (int t = 0; t < 2; t++) {
            __nv_bfloat16 hh, ll;
            split_bf16(acc[t], hh, ll);
            ohi[obase + (size_t)(tg * 2 + t) * EDIM] = hh;
            olo[obase + (size_t)(tg * 2 + t) * EDIM] = ll;
        }
    }
}

// ------------------------- residual + layernorm ------------------------------
__global__ void ln_kernel(const float* __restrict__ xq, const float* __restrict__ o2,
                          const float* __restrict__ g, const float* __restrict__ be,
                          float* __restrict__ y,
                          __nv_bfloat16* __restrict__ yhi, __nv_bfloat16* __restrict__ ylo)
{
    const int r = blockIdx.x;
    const float* xr = xq + (size_t)r * EDIM;
    const float* orow = o2 + (size_t)r * EDIM;
    const int tid = threadIdx.x;
    float v0 = xr[tid] + orow[tid];
    float v1 = xr[tid + 256] + orow[tid + 256];
    float s = v0 + v1, sq = v0 * v0 + v1 * v1;
    for (int o = 16; o >= 1; o >>= 1) {
        s  += __shfl_xor_sync(0xffffffffu, s, o);
        sq += __shfl_xor_sync(0xffffffffu, sq, o);
    }
    __shared__ float ss[8], ssq[8];
    __shared__ float mu, rstd;
    int w = tid >> 5;
    if ((tid & 31) == 0) { ss[w] = s; ssq[w] = sq; }
    __syncthreads();
    if (tid == 0) {
        float S = 0.f, SQ = 0.f;
        for (int i = 0; i < 8; i++) { S += ss[i]; SQ += ssq[i]; }
        float m = S / 512.f;
        float var = SQ / 512.f - m * m;
        mu = m; rstd = rsqrtf(var + 1e-5f);
    }
    __syncthreads();
    float y0 = (v0 - mu) * rstd * g[tid]       + be[tid];
    float y1 = (v1 - mu) * rstd * g[tid + 256] + be[tid + 256];
    y[(size_t)r * EDIM + tid]       = y0;
    y[(size_t)r * EDIM + tid + 256] = y1;
    __nv_bfloat16 h0, l0, h1, l1;
    split_bf16(y0, h0, l0); split_bf16(y1, h1, l1);
    yhi[(size_t)r * EDIM + tid]       = h0;
    ylo[(size_t)r * EDIM + tid]       = l0;
    yhi[(size_t)r * EDIM + tid + 256] = h1;
    ylo[(size_t)r * EDIM + tid + 256] = l1;
}

// ------------------------- launcher ------------------------------------------
extern "C" void kernel_launch(void* const* d_in, const int* in_sizes, int n_in,
                              void* d_out, int out_size)
{
    const float* ppf = (const float*)d_in[0];
    const float* sc  = (const float*)d_in[1];
    const float* pw  = (const float*)d_in[2];
    const float* pb  = (const float*)d_in[3];
    const float* ipw = (const float*)d_in[4];
    const float* ipb = (const float*)d_in[5];
    const float* opw = (const float*)d_in[6];
    const float* opb = (const float*)d_in[7];
    const float* lng = (const float*)d_in[8];
    const float* lnb = (const float*)d_in[9];
    const float* fw  = (const float*)d_in[10];
    const float* fb  = (const float*)d_in[11];
    float* out = (float*)d_out;

    int* idx;
    __nv_bfloat16 *wphi, *wplo, *wqhi, *wqlo, *wkvhi, *wkvlo;
    __nv_bfloat16 *wohi, *wolo, *wfhi, *wflo, *xhi, *xlo, *ohi, *olo, *yhi, *ylo;
    float *kv, *xq, *q, *o2, *y;
    cudaGetSymbolAddress((void**)&idx,   g_idx);
    cudaGetSymbolAddress((void**)&wphi,  g_wphi);
    cudaGetSymbolAddress((void**)&wplo,  g_wplo);
    cudaGetSymbolAddress((void**)&wqhi,  g_wqhi);
    cudaGetSymbolAddress((void**)&wqlo,  g_wqlo);
    cudaGetSymbolAddress((void**)&wkvhi, g_wkvhi);
    cudaGetSymbolAddress((void**)&wkvlo, g_wkvlo);
    cudaGetSymbolAddress((void**)&wohi,  g_wohi);
    cudaGetSymbolAddress((void**)&wolo,  g_wolo);
    cudaGetSymbolAddress((void**)&wfhi,  g_wfhi);
    cudaGetSymbolAddress((void**)&wflo,  g_wflo);
    cudaGetSymbolAddress((void**)&xhi,   g_xhi);
    cudaGetSymbolAddress((void**)&xlo,   g_xlo);
    cudaGetSymbolAddress((void**)&kv,    g_kv);
    cudaGetSymbolAddress((void**)&xq,    g_xq);
    cudaGetSymbolAddress((void**)&q,     g_q);
    cudaGetSymbolAddress((void**)&ohi,   g_ohi);
    cudaGetSymbolAddress((void**)&olo,   g_olo);
    cudaGetSymbolAddress((void**)&o2,    g_o2);
    cudaGetSymbolAddress((void**)&y,     g_y);
    cudaGetSymbolAddress((void**)&yhi,   g_yhi);
    cudaGetSymbolAddress((void**)&ylo,   g_ylo);

    cudaFuncSetAttribute(gather_gemm,     cudaFuncAttributeMaxDynamicSharedMemorySize, GTH_SMEM);
    cudaFuncSetAttribute(kv_gemm,         cudaFuncAttributeMaxDynamicSharedMemorySize, KV_SMEM);
    cudaFuncSetAttribute(small_gemm<0,1>, cudaFuncAttributeMaxDynamicSharedMemorySize, SGEMM_SMEM);
    cudaFuncSetAttribute(small_gemm<0,0>, cudaFuncAttributeMaxDynamicSharedMemorySize, SGEMM_SMEM);
    cudaFuncSetAttribute(small_gemm<2,0>, cudaFuncAttributeMaxDynamicSharedMemorySize, SGEMM_SMEM);
    cudaFuncSetAttribute(attn_kernel,     cudaFuncAttributeMaxDynamicSharedMemorySize, ATTN_SMEM);

    // 1) topk (hist also converts weights + zeroes g_cnt)
    topk_hist<<<128, 256>>>(sc, pw, ipw, opw, fw);
    topk_filter<<<128, 256>>>(sc);
    topk_final<<<16, 512>>>(idx);

    // 2) x = gather(ppf) @ proj_w^T + pb  (R12-proven 128x128 fused kernel)
    gather_gemm<<<dim3(64, 4), 256, GTH_SMEM>>>(wphi, wplo, pb, xq, xhi, xlo, ppf, idx);

    // 3) kv = x @ Wkv^T + b  (R12-proven 128x64, 3 CTAs/SM)
    kv_gemm<<<dim3(64, 16), 256, KV_SMEM>>>(xhi, xlo, wkvhi, wkvlo, ipb + EDIM, kv);

    // 4) q = x[:, :16] @ Wq^T + b
    small_gemm<0,1><<<dim3(4, 8), 256, SGEMM_SMEM>>>(xhi, xlo, wqhi, wqlo, ipb, nullptr, q);

    // 5) attention -> o (bf16 hi/lo)  [512 threads: 16 warps/SM]
    attn_kernel<<<128, 512, ATTN_SMEM>>>(q, kv, ohi, olo);

    // 6) out_proj
    small_gemm<0,0><<<dim3(4, 8), 256, SGEMM_SMEM>>>(ohi, olo, wohi, wolo, opb, nullptr, o2);

    // 7) residual + layernorm
    ln_kernel<<<256, 256>>>(xq, o2, lng, lnb, y, yhi, ylo);

    // 8) FFN GEMM + fused gelu + residual -> out
    small_gemm<2,0><<<dim3(4, 8), 256, SGEMM_SMEM>>>(yhi, ylo, wfhi, wflo, fb, y, out);
}